// round 14
// baseline (speedup 1.0000x reference)
#include <cuda_runtime.h>
#include <cuda_fp16.h>

#define PLANE  65536
#define TOT    262144

typedef unsigned long long ull;

__device__ __forceinline__ ull pk2(float x, float y) {
    ull r; asm("mov.b64 %0, {%1,%2};" : "=l"(r) : "f"(x), "f"(y)); return r;
}
__device__ __forceinline__ void upk2(ull v, float& x, float& y) {
    asm("mov.b64 {%0,%1}, %2;" : "=f"(x), "=f"(y) : "l"(v));
}
__device__ __forceinline__ ull ffma2(ull a, ull b, ull c) {
    ull d; asm("fma.rn.f32x2 %0, %1, %2, %3;" : "=l"(d) : "l"(a), "l"(b), "l"(c)); return d;
}
__device__ __forceinline__ unsigned f2t(float x) {
    unsigned u; asm("cvt.rna.tf32.f32 %0, %1;" : "=r"(u) : "f"(x)); return u;
}
__device__ __forceinline__ void mma8(float* d,
                                     unsigned a0, unsigned a1, unsigned a2, unsigned a3,
                                     unsigned b0, unsigned b1) {
    asm volatile("mma.sync.aligned.m16n8k8.row.col.f32.tf32.tf32.f32 "
                 "{%0,%1,%2,%3}, {%4,%5,%6,%7}, {%8,%9}, {%0,%1,%2,%3};"
                 : "+f"(d[0]), "+f"(d[1]), "+f"(d[2]), "+f"(d[3])
                 : "r"(a0), "r"(a1), "r"(a2), "r"(a3), "r"(b0), "r"(b1));
}

template<int H>
__device__ __forceinline__ float4 ldvec(const void* base, long elem) {
    if (H) {
        const __half* hp = (const __half*)base + elem;
        uint2 u = *(const uint2*)hp;
        __half2 h0 = *reinterpret_cast<__half2*>(&u.x);
        __half2 h1 = *reinterpret_cast<__half2*>(&u.y);
        float2 f0 = __half22float2(h0), f1 = __half22float2(h1);
        return make_float4(f0.x, f0.y, f1.x, f1.y);
    } else {
        return *(const float4*)((const float*)base + elem);
    }
}
template<int H>
__device__ __forceinline__ void st2v(void* base, long elem, float x, float y) {
    if (H) *(__half2*)((__half*)base + elem) = __floats2half2_rn(x, y);
    else   *(float2*)((float*)base + elem) = make_float2(x, y);
}

// ---------------- scratch ------------------------------------------------------
__device__ __half g_QKVh[1024 * 768];
__device__ __half g_psumh[16 * PLANE];
__device__ __half g_Sh[16 * PLANE];
__device__ __half g_Ph[16 * PLANE];
__device__ __half g_avph[2 * TOT];
__device__ float  g_part[4 * TOT];
__device__ float  g_res1[TOT];
__device__ float  g_res2[TOT];
__device__ __half g_ffnh[1024 * 1024];
__device__ float  g_pe2s[128 * 4];
__device__ float  g_pe2bs[4];
__device__ float  g_red[16];

// ---------------- prep: fold pe2, zero LN accumulators -------------------------
__global__ void prep_k(const float* __restrict__ pe2w, const float* __restrict__ pe2b) {
    int tid = threadIdx.x;  // 128 threads
    #pragma unroll
    for (int h = 0; h < 4; h++) {
        float s = 0.f;
        #pragma unroll 8
        for (int c = 0; c < 64; c++) s += pe2w[tid * 256 + h * 64 + c];
        g_pe2s[tid * 4 + h] = s;
    }
    if (tid < 4) {
        float s = 0.f;
        for (int c = 0; c < 64; c++) s += pe2b[tid * 64 + c];
        g_pe2bs[tid] = s;
    }
    if (tid < 16) g_red[tid] = 0.f;
}

// ---------------- PE MLP (folded), 2 rows/thread, f32x2, fp16 out --------------
__global__ void pe_k(const float* __restrict__ loc, const float* __restrict__ w1,
                     const float* __restrict__ b1) {
    __shared__ float4 sW[128];
    __shared__ ull    sS[128][4];
    __shared__ float  sB[4];
    int tid = threadIdx.x;
    if (tid < 128) {
        sW[tid] = make_float4(b1[tid], w1[tid], w1[128 + tid], w1[256 + tid]);
        float4 sv = *(const float4*)(g_pe2s + tid * 4);
        sS[tid][0] = pk2(sv.x, sv.x);
        sS[tid][1] = pk2(sv.y, sv.y);
        sS[tid][2] = pk2(sv.z, sv.z);
        sS[tid][3] = pk2(sv.w, sv.w);
    }
    if (tid < 4) sB[tid] = g_pe2bs[tid];
    __syncthreads();

    int gid = blockIdx.x * 256 + tid;       // < 131072, 2 rows each
    const float2* L = (const float2*)loc;
    float2 l0 = L[3 * gid], l1 = L[3 * gid + 1], l2 = L[3 * gid + 2];
    ull A0 = pk2(sB[0], sB[0]), A1 = pk2(sB[1], sB[1]);
    ull A2 = pk2(sB[2], sB[2]), A3 = pk2(sB[3], sB[3]);
    #pragma unroll 4
    for (int i = 0; i < 128; i++) {
        float4 w = sW[i];
        float h0 = fmaf(l1.x, w.w, fmaf(l0.y, w.z, fmaf(l0.x, w.y, w.x)));
        float h1 = fmaf(l2.y, w.w, fmaf(l2.x, w.z, fmaf(l1.y, w.y, w.x)));
        h0 = fmaxf(h0, 0.f); h1 = fmaxf(h1, 0.f);
        ull hd = pk2(h0, h1);
        A0 = ffma2(hd, sS[i][0], A0);
        A1 = ffma2(hd, sS[i][1], A1);
        A2 = ffma2(hd, sS[i][2], A2);
        A3 = ffma2(hd, sS[i][3], A3);
    }
    int r0 = 2 * gid;
    int b = r0 >> 16, m = (r0 >> 8) & 255, k2 = (r0 & 255) >> 1;
    __half2* P = (__half2*)g_psumh;
    long base = ((long)b * 4) * 32768 + (long)m * 128 + k2;
    float x, y;
    upk2(A0, x, y); P[base]             = __floats2half2_rn(x, y);
    upk2(A1, x, y); P[base + 32768]     = __floats2half2_rn(x, y);
    upk2(A2, x, y); P[base + 2 * 32768] = __floats2half2_rn(x, y);
    upk2(A3, x, y); P[base + 3 * 32768] = __floats2half2_rn(x, y);
}

// ---------------- TF32 GEMM: BM in {32,64}, BN=64, BK=32, 128 thr ---------------
#define EPI_NONE  0
#define EPI_BIAS  1
#define EPI_BRELU 2
#define EPI_SCL   3

template<int BM, int TRB, int EPI, int ASUM, int NBL, int AH, int BH, int CH, int LNA, int SRC3>
__global__ void gtc(const void* __restrict__ A, const void* __restrict__ A2,
                    const void* __restrict__ Bp0, const void* __restrict__ Bp1,
                    const void* __restrict__ Bp2,
                    const float* __restrict__ bias0, const float* __restrict__ bias1,
                    const float* __restrict__ bias2,
                    void* __restrict__ C,
                    const float* __restrict__ lnw, const float* __restrict__ lnb,
                    int KSPL, int lda, int ldb, int ldc,
                    long sAb, long sAh, long sBb, long sBh, long sCb, long sCh,
                    long spC) {
    constexpr int BN = 64, BK = 32, NTHR = 128;
    constexpr int MI = BM / 32;
    constexpr int APT = BM / 16;
    constexpr int BPT = 4;
    __shared__ unsigned As[2][BK][BM + 8];
    __shared__ unsigned Bs[2][BK][72];

    int tid = threadIdx.x, w = tid >> 5, lane = tid & 31;
    int g = lane >> 2, t = lane & 3;
    int wr = w & 1, wc = w >> 1;
    int nb = blockIdx.x % NBL, sp = blockIdx.x / NBL;
    int z = blockIdx.z, zb = z >> 2, zh = z & 3;
    long kb0 = (long)sp * KSPL;

    const void* Bsel = Bp0;
    const float* bias = bias0;
    int bcol0;
    if (SRC3) {
        int sel = blockIdx.x >> 2;
        Bsel = (sel == 0) ? Bp0 : (sel == 1 ? Bp1 : Bp2);
        bias = (sel == 0) ? bias0 : (sel == 1 ? bias1 : bias2);
        bcol0 = (blockIdx.x & 3) * BN;
    } else {
        bcol0 = nb * BN;
    }

    long aBase = zb * sAb + zh * sAh + (long)(blockIdx.y * BM) * lda + kb0;
    long bBase;
    if (TRB) bBase = zb * sBb + zh * sBh + (long)(nb * BN) * ldb + kb0;
    else     bBase = zb * sBb + zh * sBh + kb0 * (long)ldb + bcol0;

    int bat = (blockIdx.y * BM) >> 8;
    float lnm = 0.f, lnri = 0.f;
    if (LNA) {
        lnm = g_red[bat * 2] * (1.f / 65536.f);
        float var = g_red[bat * 2 + 1] * (1.f / 65536.f) - lnm * lnm;
        lnri = rsqrtf(var + 1e-5f);
    }

    int aR[APT], aC[APT], bR[BPT], bC[BPT];
    #pragma unroll
    for (int i = 0; i < APT; i++) {
        int s = tid + i * NTHR;
        aR[i] = s >> 3; aC[i] = (s & 7) * 4;
    }
    #pragma unroll
    for (int i = 0; i < BPT; i++) {
        int s = tid + i * NTHR;
        if (TRB) { bR[i] = s >> 3; bC[i] = (s & 7) * 4; }
        else     { bR[i] = s >> 4; bC[i] = (s & 15) * 4; }
    }
    float4 rA[APT], rB[BPT];

    auto ldg = [&](int kt) {
        int kb = kt * BK;
        #pragma unroll
        for (int i = 0; i < APT; i++) {
            long off = aBase + (long)aR[i] * lda + kb + aC[i];
            float4 v = ldvec<AH>(A, off);
            if (ASUM) {
                float4 v2 = ldvec<AH>(A2, off);
                v.x += v2.x; v.y += v2.y; v.z += v2.z; v.w += v2.w;
            }
            if (LNA) {
                int p = (int)(((long)(blockIdx.y * BM + aR[i]) * lda + kb + aC[i]) & 65535);
                float4 wv = *(const float4*)(lnw + p);
                float4 bv = *(const float4*)(lnb + p);
                v.x = (v.x - lnm) * lnri * wv.x + bv.x;
                v.y = (v.y - lnm) * lnri * wv.y + bv.y;
                v.z = (v.z - lnm) * lnri * wv.z + bv.z;
                v.w = (v.w - lnm) * lnri * wv.w + bv.w;
            }
            rA[i] = v;
        }
        #pragma unroll
        for (int i = 0; i < BPT; i++) {
            long off;
            if (TRB) off = bBase + (long)bR[i] * ldb + kb + bC[i];
            else     off = bBase + (long)(kb + bR[i]) * ldb + bC[i];
            rB[i] = ldvec<BH>(Bsel, off);
        }
    };
    auto sts = [&](int bf) {
        #pragma unroll
        for (int i = 0; i < APT; i++) {
            float4 v = rA[i];
            As[bf][aC[i] + 0][aR[i]] = f2t(v.x);
            As[bf][aC[i] + 1][aR[i]] = f2t(v.y);
            As[bf][aC[i] + 2][aR[i]] = f2t(v.z);
            As[bf][aC[i] + 3][aR[i]] = f2t(v.w);
        }
        #pragma unroll
        for (int i = 0; i < BPT; i++) {
            float4 v = rB[i];
            if (TRB) {
                Bs[bf][bC[i] + 0][bR[i]] = f2t(v.x);
                Bs[bf][bC[i] + 1][bR[i]] = f2t(v.y);
                Bs[bf][bC[i] + 2][bR[i]] = f2t(v.z);
                Bs[bf][bC[i] + 3][bR[i]] = f2t(v.w);
            } else {
                *(uint4*)&Bs[bf][bR[i]][bC[i]] =
                    make_uint4(f2t(v.x), f2t(v.y), f2t(v.z), f2t(v.w));
            }
        }
    };

    float acc[MI][4][4] = {};
    int wm = wr * (MI * 16), wn = wc * 32;
    int KT = KSPL / BK, buf = 0;

    ldg(0); sts(0); __syncthreads();
    for (int kt = 0; kt < KT; kt++) {
        if (kt + 1 < KT) ldg(kt + 1);
        #pragma unroll
        for (int ks = 0; ks < BK / 8; ks++) {
            unsigned af[MI][4], bfr[4][2];
            #pragma unroll
            for (int mi = 0; mi < MI; mi++) {
                int m0 = wm + mi * 16 + g;
                af[mi][0] = As[buf][ks * 8 + t][m0];
                af[mi][1] = As[buf][ks * 8 + t][m0 + 8];
                af[mi][2] = As[buf][ks * 8 + t + 4][m0];
                af[mi][3] = As[buf][ks * 8 + t + 4][m0 + 8];
            }
            #pragma unroll
            for (int ni = 0; ni < 4; ni++) {
                int n0 = wn + ni * 8 + g;
                bfr[ni][0] = Bs[buf][ks * 8 + t][n0];
                bfr[ni][1] = Bs[buf][ks * 8 + t + 4][n0];
            }
            #pragma unroll
            for (int mi = 0; mi < MI; mi++)
                #pragma unroll
                for (int ni = 0; ni < 4; ni++)
                    mma8(acc[mi][ni], af[mi][0], af[mi][1], af[mi][2], af[mi][3],
                         bfr[ni][0], bfr[ni][1]);
        }
        if (kt + 1 < KT) { sts(buf ^ 1); __syncthreads(); buf ^= 1; }
    }

    long Cb = zb * sCb + zh * sCh + (long)sp * spC;
    int row0 = blockIdx.y * BM + wm;
    int ocol0 = (SRC3 ? blockIdx.x * BN : nb * BN) + wn;
    int bcolw = bcol0 + wn;
    #pragma unroll
    for (int mi = 0; mi < MI; mi++) {
        #pragma unroll
        for (int ni = 0; ni < 4; ni++) {
            int cl = ni * 8 + 2 * t;
            #pragma unroll
            for (int half = 0; half < 2; half++) {
                int r = row0 + mi * 16 + g + half * 8;
                float x = acc[mi][ni][half * 2], y = acc[mi][ni][half * 2 + 1];
                long idx = Cb + (long)r * ldc + ocol0 + cl;
                if (EPI == EPI_BIAS || EPI == EPI_BRELU) {
                    float2 bv = *(const float2*)(bias + bcolw + cl);
                    x += bv.x; y += bv.y;
                    if (EPI == EPI_BRELU) { x = fmaxf(x, 0.f); y = fmaxf(y, 0.f); }
                }
                if (EPI == EPI_SCL) { x *= 0.125f; y *= 0.125f; }
                st2v<CH>(C, idx, x, y);
            }
        }
    }
}

// ---------------- softmax: arg = S(half) + 0.125*psum(half); fp16 probs --------
__global__ void softmax_k(const __half* __restrict__ S, const __half* __restrict__ psum,
                          __half* __restrict__ P) {
    int t = threadIdx.x, warp = t >> 5, lane = t & 31;
    long row = (long)blockIdx.x * 8 + warp;
    const __half2* sp = (const __half2*)(S + row * 256);
    const __half2* pp = (const __half2*)(psum + row * 256);
    float2 s0 = __half22float2(sp[2 * lane]);
    float2 s1 = __half22float2(sp[2 * lane + 1]);
    float2 s2 = __half22float2(sp[64 + 2 * lane]);
    float2 s3 = __half22float2(sp[64 + 2 * lane + 1]);
    float2 p0 = __half22float2(pp[2 * lane]);
    float2 p1 = __half22float2(pp[2 * lane + 1]);
    float2 p2 = __half22float2(pp[64 + 2 * lane]);
    float2 p3 = __half22float2(pp[64 + 2 * lane + 1]);
    float4 a = make_float4(s0.x + 0.125f * p0.x, s0.y + 0.125f * p0.y,
                           s1.x + 0.125f * p1.x, s1.y + 0.125f * p1.y);
    float4 b = make_float4(s2.x + 0.125f * p2.x, s2.y + 0.125f * p2.y,
                           s3.x + 0.125f * p3.x, s3.y + 0.125f * p3.y);
    float mx = fmaxf(fmaxf(fmaxf(a.x, a.y), fmaxf(a.z, a.w)),
                     fmaxf(fmaxf(b.x, b.y), fmaxf(b.z, b.w)));
    #pragma unroll
    for (int o = 16; o > 0; o >>= 1) mx = fmaxf(mx, __shfl_xor_sync(0xffffffffu, mx, o));
    a.x = __expf(a.x - mx); a.y = __expf(a.y - mx); a.z = __expf(a.z - mx); a.w = __expf(a.w - mx);
    b.x = __expf(b.x - mx); b.y = __expf(b.y - mx); b.z = __expf(b.z - mx); b.w = __expf(b.w - mx);
    float sm = a.x + a.y + a.z + a.w + b.x + b.y + b.z + b.w;
    #pragma unroll
    for (int o = 16; o > 0; o >>= 1) sm += __shfl_xor_sync(0xffffffffu, sm, o);
    float inv = 1.f / sm;
    __half2* hp = (__half2*)(P + row * 256);
    hp[2 * lane]          = __floats2half2_rn(a.x * inv, a.y * inv);
    hp[2 * lane + 1]      = __floats2half2_rn(a.z * inv, a.w * inv);
    hp[64 + 2 * lane]     = __floats2half2_rn(b.x * inv, b.y * inv);
    hp[64 + 2 * lane + 1] = __floats2half2_rn(b.z * inv, b.w * inv);
}

// ---------------- split-K reduce + bias + residual (+LN on residual) + stats ----
template<int PPART, int LNRES, int OFF>
__global__ void redres_k(const float* __restrict__ parts, const float* __restrict__ bias,
                         const float* __restrict__ R, float* __restrict__ X,
                         const float* __restrict__ lnw, const float* __restrict__ lnb) {
    __shared__ float shr[2][8];
    int gid = blockIdx.x * 256 + threadIdx.x;       // float4 index < 65536
    int bt = gid >> 14;
    float lnm = 0.f, lnri = 0.f;
    if (LNRES) {
        lnm = g_red[bt * 2] * (1.f / 65536.f);
        float var = g_red[bt * 2 + 1] * (1.f / 65536.f) - lnm * lnm;
        lnri = rsqrtf(var + 1e-5f);
    }
    const float4* pp = (const float4*)parts;
    float4 a = pp[gid];
    #pragma unroll
    for (int p = 1; p < PPART; p++) {
        float4 v = pp[gid + p * (TOT / 4)];
        a.x += v.x; a.y += v.y; a.z += v.z; a.w += v.w;
    }
    float4 bv = ((const float4*)bias)[gid & 63];
    float4 rv = ((const float4*)R)[gid];
    if (LNRES) {
        int p = gid & 16383;
        float4 wv = ((const float4*)lnw)[p];
        float4 lv = ((const float4*)lnb)[p];
        rv.x = (rv.x - lnm) * lnri * wv.x + lv.x;
        rv.y = (rv.y - lnm) * lnri * wv.y + lv.y;
        rv.z = (rv.z - lnm) * lnri * wv.z + lv.z;
        rv.w = (rv.w - lnm) * lnri * wv.w + lv.w;
    }
    a.x += bv.x + rv.x; a.y += bv.y + rv.y; a.z += bv.z + rv.z; a.w += bv.w + rv.w;
    ((float4*)X)[gid] = a;
    float s = a.x + a.y + a.z + a.w;
    float q = a.x * a.x + a.y * a.y + a.z * a.z + a.w * a.w;
    #pragma unroll
    for (int o = 16; o > 0; o >>= 1) {
        s += __shfl_xor_sync(0xffffffffu, s, o);
        q += __shfl_xor_sync(0xffffffffu, q, o);
    }
    int lane = threadIdx.x & 31, wp = threadIdx.x >> 5;
    if (lane == 0) { shr[0][wp] = s; shr[1][wp] = q; }
    __syncthreads();
    if (threadIdx.x == 0) {
        float ts = 0.f, tq = 0.f;
        #pragma unroll
        for (int i = 0; i < 8; i++) { ts += shr[0][i]; tq += shr[1][i]; }
        atomicAdd(&g_red[OFF + bt * 2], ts);
        atomicAdd(&g_red[OFF + bt * 2 + 1], tq);
    }
}

// ---------------- LayerNorm apply (final) ---------------------------------------
__global__ void ln_k(const float* __restrict__ X, const float* __restrict__ w,
                     const float* __restrict__ b, float* __restrict__ out) {
    int gid = blockIdx.x * blockDim.x + threadIdx.x;   // < 65536 float4s
    int bt = gid >> 14;
    float m   = g_red[8 + bt * 2] * (1.f / 65536.f);
    float var = g_red[8 + bt * 2 + 1] * (1.f / 65536.f) - m * m;
    float ri  = rsqrtf(var + 1e-5f);
    int p = gid & 16383;
    float4 x  = ((const float4*)X)[gid];
    float4 wv = ((const float4*)w)[p];
    float4 bv = ((const float4*)b)[p];
    float4 o;
    o.x = (x.x - m) * ri * wv.x + bv.x;
    o.y = (x.y - m) * ri * wv.y + bv.y;
    o.z = (x.z - m) * ri * wv.z + bv.z;
    o.w = (x.w - m) * ri * wv.w + bv.w;
    ((float4*)out)[gid] = o;
}

// ---------------- launch ----------------------------------------------------------
extern "C" void kernel_launch(void* const* d_in, const int* in_sizes, int n_in,
                              void* d_out, int out_size) {
    const float* feat = (const float*)d_in[0];
    const float* loc  = (const float*)d_in[1];
    const float* Kw   = (const float*)d_in[2];
    const float* Kb   = (const float*)d_in[3];
    const float* Qw   = (const float*)d_in[4];
    const float* Qb   = (const float*)d_in[5];
    const float* Vw   = (const float*)d_in[6];
    const float* Vb   = (const float*)d_in[7];
    const float* Fw   = (const float*)d_in[8];
    const float* Fb   = (const float*)d_in[9];
    const float* pe1w = (const float*)d_in[10];
    const float* pe1b = (const float*)d_in[11];
    const float* pe2w = (const float*)d_in[12];
    const float* pe2b = (const float*)d_in[13];
    const float* f1w  = (const float*)d_in[14];
    const float* f1b  = (const float*)d_in[15];
    const float* f2w  = (const float*)d_in[16];
    const float* f2b  = (const float*)d_in[17];
    const float* ln1w = (const float*)d_in[18];
    const float* ln1b = (const float*)d_in[19];
    const float* ln2w = (const float*)d_in[20];
    const float* ln2b = (const float*)d_in[21];
    float* out = (float*)d_out;

    __half *pQKV, *pPsum, *pSh, *pPh, *pAvp, *pFfnh;
    float *pPart, *pRes1, *pRes2;
    cudaGetSymbolAddress((void**)&pQKV, g_QKVh);
    cudaGetSymbolAddress((void**)&pPsum, g_psumh);
    cudaGetSymbolAddress((void**)&pSh, g_Sh);
    cudaGetSymbolAddress((void**)&pPh, g_Ph);
    cudaGetSymbolAddress((void**)&pAvp, g_avph);
    cudaGetSymbolAddress((void**)&pFfnh, g_ffnh);
    cudaGetSymbolAddress((void**)&pPart, g_part);
    cudaGetSymbolAddress((void**)&pRes1, g_res1);
    cudaGetSymbolAddress((void**)&pRes2, g_res2);

    static cudaStream_t sPE = nullptr, sV = nullptr;
    static cudaEvent_t evFork = nullptr, evJoin = nullptr, evV = nullptr;
    if (sPE == nullptr) {
        cudaStreamCreateWithFlags(&sPE, cudaStreamNonBlocking);
        cudaStreamCreateWithFlags(&sV, cudaStreamNonBlocking);
        cudaEventCreateWithFlags(&evFork, cudaEventDisableTiming);
        cudaEventCreateWithFlags(&evJoin, cudaEventDisableTiming);
        cudaEventCreateWithFlags(&evV, cudaEventDisableTiming);
    }

    // ---- fork ----
    cudaEventRecord(evFork, 0);
    cudaStreamWaitEvent(sPE, evFork, 0);
    cudaStreamWaitEvent(sV, evFork, 0);

    // PE branch
    prep_k<<<1, 128, 0, sPE>>>(pe2w, pe2b);
    pe_k<<<512, 256, 0, sPE>>>(loc, pe1w, pe1b);
    cudaEventRecord(evJoin, sPE);

    // V projection branch: [1024,256] @ Vw -> QKVh cols [512,768)
    gtc<64, 0, EPI_BIAS, 0, 4, 0, 0, 1, 0, 0><<<dim3(4, 16, 1), 128, 0, sV>>>(
        feat, nullptr, Vw, nullptr, nullptr, Vb, nullptr, nullptr,
        pQKV + 512, nullptr, nullptr,
        256, 256, 256, 768, 0, 0, 0, 0, 0, 0, 0);
    cudaEventRecord(evV, sV);

    // ---- main branch ----
    // QK: [1024,256] @ {Qw|Kw} -> QKVh cols [0,512), BM=32, grid 256
    gtc<32, 0, EPI_BIAS, 0, 8, 0, 0, 1, 0, 1><<<dim3(8, 32, 1), 128>>>(
        feat, nullptr, Qw, Kw, nullptr, Qb, Kb, nullptr,
        pQKV, nullptr, nullptr,
        256, 256, 256, 768, 0, 0, 0, 0, 0, 0, 0);

    // scores: per (b,h) K-rows · Q-rows^T * 0.125 -> Sh (half), grid 512
    gtc<32, 1, EPI_SCL, 0, 4, 1, 1, 1, 0, 0><<<dim3(4, 8, 16), 128>>>(
        pQKV + 256, nullptr, pQKV, nullptr, nullptr, nullptr, nullptr, nullptr,
        pSh, nullptr, nullptr,
        64, 768, 768, 256, 196608, 64, 196608, 64, 262144, 65536, 0);

    // join PE, then softmax (adds 0.125*psum)
    cudaStreamWaitEvent(0, evJoin, 0);
    softmax_k<<<512, 256>>>(pSh, pPsum, pPh);

    // join V, then AV: attn(half) @ V(half), split-K 2 (BM=32, grid 256)
    cudaStreamWaitEvent(0, evV, 0);
    gtc<32, 0, EPI_NONE, 0, 1, 1, 1, 1, 0, 0><<<dim3(2, 8, 16), 128>>>(
        pPh, nullptr, pQKV + 512, nullptr, nullptr, nullptr, nullptr, nullptr,
        pAvp, nullptr, nullptr,
        128, 256, 768, 256, 262144, 65536, 196608, 64, 65536, 64, TOT);

    // output projection: A = avp0+avp1 (half), split-K 2 -> part fp32
    gtc<64, 0, EPI_NONE, 1, 4, 1, 0, 0, 0, 0><<<dim3(8, 16, 1), 128>>>(
        pAvp, pAvp + TOT, Fw, nullptr, nullptr, nullptr, nullptr, nullptr,
        pPart, nullptr, nullptr,
        128, 256, 256, 256, 0, 0, 0, 0, 0, 0, TOT);

    // reduce + Fb + feat residual -> res1, LN1 stats -> red[0..7]
    redres_k<2, 0, 0><<<256, 256>>>(pPart, Fb, feat, pRes1, nullptr, nullptr);

    // FFN1: A = LN1(res1) on load; bias+relu -> ffnh (half)
    gtc<64, 0, EPI_BRELU, 0, 16, 0, 0, 1, 1, 0><<<dim3(16, 16, 1), 128>>>(
        pRes1, nullptr, f1w, nullptr, nullptr, f1b, nullptr, nullptr,
        pFfnh, ln1w, ln1b,
        256, 256, 1024, 1024, 0, 0, 0, 0, 0, 0, 0);

    // FFN2: A = ffnh (half), split-K 4 -> part fp32
    gtc<64, 0, EPI_NONE, 0, 4, 1, 0, 0, 0, 0><<<dim3(16, 16, 1), 128>>>(
        pFfnh, nullptr, f2w, nullptr, nullptr, nullptr, nullptr, nullptr,
        pPart, nullptr, nullptr,
        256, 1024, 256, 256, 0, 0, 0, 0, 0, 0, TOT);

    // reduce + f2b + LN1(res1) residual -> res2, LN2 stats -> red[8..15]
    redres_k<4, 1, 8><<<256, 256>>>(pPart, f2b, pRes1, pRes2, ln1w, ln1b);

    // final LN2 -> out
    ln_k<<<256, 256>>>(pRes2, ln2w, ln2b, out);
}

// round 15
// speedup vs baseline: 1.0422x; 1.0422x over previous
#include <cuda_runtime.h>
#include <cuda_fp16.h>

#define PLANE  65536
#define TOT    262144

typedef unsigned long long ull;

__device__ __forceinline__ ull pk2(float x, float y) {
    ull r; asm("mov.b64 %0, {%1,%2};" : "=l"(r) : "f"(x), "f"(y)); return r;
}
__device__ __forceinline__ void upk2(ull v, float& x, float& y) {
    asm("mov.b64 {%0,%1}, %2;" : "=f"(x), "=f"(y) : "l"(v));
}
__device__ __forceinline__ ull ffma2(ull a, ull b, ull c) {
    ull d; asm("fma.rn.f32x2 %0, %1, %2, %3;" : "=l"(d) : "l"(a), "l"(b), "l"(c)); return d;
}
__device__ __forceinline__ unsigned f2t(float x) {
    unsigned u; asm("cvt.rna.tf32.f32 %0, %1;" : "=r"(u) : "f"(x)); return u;
}
__device__ __forceinline__ void mma8(float* d,
                                     unsigned a0, unsigned a1, unsigned a2, unsigned a3,
                                     unsigned b0, unsigned b1) {
    asm volatile("mma.sync.aligned.m16n8k8.row.col.f32.tf32.tf32.f32 "
                 "{%0,%1,%2,%3}, {%4,%5,%6,%7}, {%8,%9}, {%0,%1,%2,%3};"
                 : "+f"(d[0]), "+f"(d[1]), "+f"(d[2]), "+f"(d[3])
                 : "r"(a0), "r"(a1), "r"(a2), "r"(a3), "r"(b0), "r"(b1));
}

template<int H>
__device__ __forceinline__ float4 ldvec(const void* base, long elem) {
    if (H) {
        const __half* hp = (const __half*)base + elem;
        uint2 u = *(const uint2*)hp;
        __half2 h0 = *reinterpret_cast<__half2*>(&u.x);
        __half2 h1 = *reinterpret_cast<__half2*>(&u.y);
        float2 f0 = __half22float2(h0), f1 = __half22float2(h1);
        return make_float4(f0.x, f0.y, f1.x, f1.y);
    } else {
        return *(const float4*)((const float*)base + elem);
    }
}
template<int H>
__device__ __forceinline__ void st2v(void* base, long elem, float x, float y) {
    if (H) *(__half2*)((__half*)base + elem) = __floats2half2_rn(x, y);
    else   *(float2*)((float*)base + elem) = make_float2(x, y);
}

// ---------------- scratch ------------------------------------------------------
__device__ __half g_QKVh[1024 * 768];
__device__ __half g_psumh[16 * PLANE];
__device__ __half g_Sh[16 * PLANE];
__device__ __half g_Ph[16 * PLANE];
__device__ __half g_avph[2 * TOT];
__device__ float  g_part[4 * TOT];
__device__ float  g_res1[TOT];
__device__ float  g_res2[TOT];
__device__ __half g_ffnh[1024 * 1024];
__device__ float  g_pe2s[128 * 4];
__device__ float  g_pe2bs[4];
__device__ float  g_red[16];

// ---------------- prep: fold pe2, zero LN accumulators -------------------------
__global__ void prep_k(const float* __restrict__ pe2w, const float* __restrict__ pe2b) {
    int tid = threadIdx.x;  // 128 threads
    #pragma unroll
    for (int h = 0; h < 4; h++) {
        float s = 0.f;
        #pragma unroll 8
        for (int c = 0; c < 64; c++) s += pe2w[tid * 256 + h * 64 + c];
        g_pe2s[tid * 4 + h] = s;
    }
    if (tid < 4) {
        float s = 0.f;
        for (int c = 0; c < 64; c++) s += pe2b[tid * 64 + c];
        g_pe2bs[tid] = s;
    }
    if (tid < 16) g_red[tid] = 0.f;
}

// ---------------- PE MLP (folded), 2 rows/thread, f32x2, fp16 out --------------
__global__ void pe_k(const float* __restrict__ loc, const float* __restrict__ w1,
                     const float* __restrict__ b1) {
    __shared__ float4 sW[128];
    __shared__ ull    sS[128][4];
    __shared__ float  sB[4];
    int tid = threadIdx.x;
    if (tid < 128) {
        sW[tid] = make_float4(b1[tid], w1[tid], w1[128 + tid], w1[256 + tid]);
        float4 sv = *(const float4*)(g_pe2s + tid * 4);
        sS[tid][0] = pk2(sv.x, sv.x);
        sS[tid][1] = pk2(sv.y, sv.y);
        sS[tid][2] = pk2(sv.z, sv.z);
        sS[tid][3] = pk2(sv.w, sv.w);
    }
    if (tid < 4) sB[tid] = g_pe2bs[tid];
    __syncthreads();

    int gid = blockIdx.x * 256 + tid;       // < 131072, 2 rows each
    const float2* L = (const float2*)loc;
    float2 l0 = L[3 * gid], l1 = L[3 * gid + 1], l2 = L[3 * gid + 2];
    ull A0 = pk2(sB[0], sB[0]), A1 = pk2(sB[1], sB[1]);
    ull A2 = pk2(sB[2], sB[2]), A3 = pk2(sB[3], sB[3]);
    #pragma unroll 4
    for (int i = 0; i < 128; i++) {
        float4 w = sW[i];
        float h0 = fmaf(l1.x, w.w, fmaf(l0.y, w.z, fmaf(l0.x, w.y, w.x)));
        float h1 = fmaf(l2.y, w.w, fmaf(l2.x, w.z, fmaf(l1.y, w.y, w.x)));
        h0 = fmaxf(h0, 0.f); h1 = fmaxf(h1, 0.f);
        ull hd = pk2(h0, h1);
        A0 = ffma2(hd, sS[i][0], A0);
        A1 = ffma2(hd, sS[i][1], A1);
        A2 = ffma2(hd, sS[i][2], A2);
        A3 = ffma2(hd, sS[i][3], A3);
    }
    int r0 = 2 * gid;
    int b = r0 >> 16, m = (r0 >> 8) & 255, k2 = (r0 & 255) >> 1;
    __half2* P = (__half2*)g_psumh;
    long base = ((long)b * 4) * 32768 + (long)m * 128 + k2;
    float x, y;
    upk2(A0, x, y); P[base]             = __floats2half2_rn(x, y);
    upk2(A1, x, y); P[base + 32768]     = __floats2half2_rn(x, y);
    upk2(A2, x, y); P[base + 2 * 32768] = __floats2half2_rn(x, y);
    upk2(A3, x, y); P[base + 3 * 32768] = __floats2half2_rn(x, y);
}

// ---------------- TF32 GEMM: BM in {32,64}, BN=64, BK=32, 128 thr ---------------
#define EPI_NONE  0
#define EPI_BIAS  1
#define EPI_BRELU 2
#define EPI_SCL   3

template<int BM, int TRB, int EPI, int ASUM, int NBL, int AH, int BH, int CH, int LNA, int SRC3>
__global__ void gtc(const void* __restrict__ A, const void* __restrict__ A2,
                    const void* __restrict__ Bp0, const void* __restrict__ Bp1,
                    const void* __restrict__ Bp2,
                    const float* __restrict__ bias0, const float* __restrict__ bias1,
                    const float* __restrict__ bias2,
                    void* __restrict__ C,
                    const float* __restrict__ lnw, const float* __restrict__ lnb,
                    int KSPL, int lda, int ldb, int ldc,
                    long sAb, long sAh, long sBb, long sBh, long sCb, long sCh,
                    long spC) {
    constexpr int BN = 64, BK = 32, NTHR = 128;
    constexpr int MI = BM / 32;
    constexpr int APT = BM / 16;
    constexpr int BPT = 4;
    __shared__ unsigned As[2][BK][BM + 8];
    __shared__ unsigned Bs[2][BK][72];

    int tid = threadIdx.x, w = tid >> 5, lane = tid & 31;
    int g = lane >> 2, t = lane & 3;
    int wr = w & 1, wc = w >> 1;
    int nb = blockIdx.x % NBL, sp = blockIdx.x / NBL;
    int z = blockIdx.z, zb = z >> 2, zh = z & 3;
    long kb0 = (long)sp * KSPL;

    const void* Bsel = Bp0;
    const float* bias = bias0;
    int bcol0;
    if (SRC3) {
        int sel = blockIdx.x >> 2;
        Bsel = (sel == 0) ? Bp0 : (sel == 1 ? Bp1 : Bp2);
        bias = (sel == 0) ? bias0 : (sel == 1 ? bias1 : bias2);
        bcol0 = (blockIdx.x & 3) * BN;
    } else {
        bcol0 = nb * BN;
    }

    long aBase = zb * sAb + zh * sAh + (long)(blockIdx.y * BM) * lda + kb0;
    long bBase;
    if (TRB) bBase = zb * sBb + zh * sBh + (long)(nb * BN) * ldb + kb0;
    else     bBase = zb * sBb + zh * sBh + kb0 * (long)ldb + bcol0;

    int bat = (blockIdx.y * BM) >> 8;
    float lnm = 0.f, lnri = 0.f;
    if (LNA) {
        lnm = g_red[bat * 2] * (1.f / 65536.f);
        float var = g_red[bat * 2 + 1] * (1.f / 65536.f) - lnm * lnm;
        lnri = rsqrtf(var + 1e-5f);
    }

    int aR[APT], aC[APT], bR[BPT], bC[BPT];
    #pragma unroll
    for (int i = 0; i < APT; i++) {
        int s = tid + i * NTHR;
        aR[i] = s >> 3; aC[i] = (s & 7) * 4;
    }
    #pragma unroll
    for (int i = 0; i < BPT; i++) {
        int s = tid + i * NTHR;
        if (TRB) { bR[i] = s >> 3; bC[i] = (s & 7) * 4; }
        else     { bR[i] = s >> 4; bC[i] = (s & 15) * 4; }
    }
    float4 rA[APT], rB[BPT];

    auto ldg = [&](int kt) {
        int kb = kt * BK;
        #pragma unroll
        for (int i = 0; i < APT; i++) {
            long off = aBase + (long)aR[i] * lda + kb + aC[i];
            float4 v = ldvec<AH>(A, off);
            if (ASUM) {
                float4 v2 = ldvec<AH>(A2, off);
                v.x += v2.x; v.y += v2.y; v.z += v2.z; v.w += v2.w;
            }
            if (LNA) {
                int p = (int)(((long)(blockIdx.y * BM + aR[i]) * lda + kb + aC[i]) & 65535);
                float4 wv = *(const float4*)(lnw + p);
                float4 bv = *(const float4*)(lnb + p);
                v.x = (v.x - lnm) * lnri * wv.x + bv.x;
                v.y = (v.y - lnm) * lnri * wv.y + bv.y;
                v.z = (v.z - lnm) * lnri * wv.z + bv.z;
                v.w = (v.w - lnm) * lnri * wv.w + bv.w;
            }
            rA[i] = v;
        }
        #pragma unroll
        for (int i = 0; i < BPT; i++) {
            long off;
            if (TRB) off = bBase + (long)bR[i] * ldb + kb + bC[i];
            else     off = bBase + (long)(kb + bR[i]) * ldb + bC[i];
            rB[i] = ldvec<BH>(Bsel, off);
        }
    };
    auto sts = [&](int bf) {
        #pragma unroll
        for (int i = 0; i < APT; i++) {
            float4 v = rA[i];
            As[bf][aC[i] + 0][aR[i]] = f2t(v.x);
            As[bf][aC[i] + 1][aR[i]] = f2t(v.y);
            As[bf][aC[i] + 2][aR[i]] = f2t(v.z);
            As[bf][aC[i] + 3][aR[i]] = f2t(v.w);
        }
        #pragma unroll
        for (int i = 0; i < BPT; i++) {
            float4 v = rB[i];
            if (TRB) {
                Bs[bf][bC[i] + 0][bR[i]] = f2t(v.x);
                Bs[bf][bC[i] + 1][bR[i]] = f2t(v.y);
                Bs[bf][bC[i] + 2][bR[i]] = f2t(v.z);
                Bs[bf][bC[i] + 3][bR[i]] = f2t(v.w);
            } else {
                *(uint4*)&Bs[bf][bR[i]][bC[i]] =
                    make_uint4(f2t(v.x), f2t(v.y), f2t(v.z), f2t(v.w));
            }
        }
    };

    float acc[MI][4][4] = {};
    int wm = wr * (MI * 16), wn = wc * 32;
    int KT = KSPL / BK, buf = 0;

    ldg(0); sts(0); __syncthreads();
    for (int kt = 0; kt < KT; kt++) {
        if (kt + 1 < KT) ldg(kt + 1);
        #pragma unroll
        for (int ks = 0; ks < BK / 8; ks++) {
            unsigned af[MI][4], bfr[4][2];
            #pragma unroll
            for (int mi = 0; mi < MI; mi++) {
                int m0 = wm + mi * 16 + g;
                af[mi][0] = As[buf][ks * 8 + t][m0];
                af[mi][1] = As[buf][ks * 8 + t][m0 + 8];
                af[mi][2] = As[buf][ks * 8 + t + 4][m0];
                af[mi][3] = As[buf][ks * 8 + t + 4][m0 + 8];
            }
            #pragma unroll
            for (int ni = 0; ni < 4; ni++) {
                int n0 = wn + ni * 8 + g;
                bfr[ni][0] = Bs[buf][ks * 8 + t][n0];
                bfr[ni][1] = Bs[buf][ks * 8 + t + 4][n0];
            }
            #pragma unroll
            for (int mi = 0; mi < MI; mi++)
                #pragma unroll
                for (int ni = 0; ni < 4; ni++)
                    mma8(acc[mi][ni], af[mi][0], af[mi][1], af[mi][2], af[mi][3],
                         bfr[ni][0], bfr[ni][1]);
        }
        if (kt + 1 < KT) { sts(buf ^ 1); __syncthreads(); buf ^= 1; }
    }

    long Cb = zb * sCb + zh * sCh + (long)sp * spC;
    int row0 = blockIdx.y * BM + wm;
    int ocol0 = (SRC3 ? blockIdx.x * BN : nb * BN) + wn;
    int bcolw = bcol0 + wn;
    #pragma unroll
    for (int mi = 0; mi < MI; mi++) {
        #pragma unroll
        for (int ni = 0; ni < 4; ni++) {
            int cl = ni * 8 + 2 * t;
            #pragma unroll
            for (int half = 0; half < 2; half++) {
                int r = row0 + mi * 16 + g + half * 8;
                float x = acc[mi][ni][half * 2], y = acc[mi][ni][half * 2 + 1];
                long idx = Cb + (long)r * ldc + ocol0 + cl;
                if (EPI == EPI_BIAS || EPI == EPI_BRELU) {
                    float2 bv = *(const float2*)(bias + bcolw + cl);
                    x += bv.x; y += bv.y;
                    if (EPI == EPI_BRELU) { x = fmaxf(x, 0.f); y = fmaxf(y, 0.f); }
                }
                if (EPI == EPI_SCL) { x *= 0.125f; y *= 0.125f; }
                st2v<CH>(C, idx, x, y);
            }
        }
    }
}

// ---------------- softmax: arg = S(half) + 0.125*psum(half); fp16 probs --------
__global__ void softmax_k(const __half* __restrict__ S, const __half* __restrict__ psum,
                          __half* __restrict__ P) {
    int t = threadIdx.x, warp = t >> 5, lane = t & 31;
    long row = (long)blockIdx.x * 8 + warp;
    const __half2* sp = (const __half2*)(S + row * 256);
    const __half2* pp = (const __half2*)(psum + row * 256);
    float2 s0 = __half22float2(sp[2 * lane]);
    float2 s1 = __half22float2(sp[2 * lane + 1]);
    float2 s2 = __half22float2(sp[64 + 2 * lane]);
    float2 s3 = __half22float2(sp[64 + 2 * lane + 1]);
    float2 p0 = __half22float2(pp[2 * lane]);
    float2 p1 = __half22float2(pp[2 * lane + 1]);
    float2 p2 = __half22float2(pp[64 + 2 * lane]);
    float2 p3 = __half22float2(pp[64 + 2 * lane + 1]);
    float4 a = make_float4(s0.x + 0.125f * p0.x, s0.y + 0.125f * p0.y,
                           s1.x + 0.125f * p1.x, s1.y + 0.125f * p1.y);
    float4 b = make_float4(s2.x + 0.125f * p2.x, s2.y + 0.125f * p2.y,
                           s3.x + 0.125f * p3.x, s3.y + 0.125f * p3.y);
    float mx = fmaxf(fmaxf(fmaxf(a.x, a.y), fmaxf(a.z, a.w)),
                     fmaxf(fmaxf(b.x, b.y), fmaxf(b.z, b.w)));
    #pragma unroll
    for (int o = 16; o > 0; o >>= 1) mx = fmaxf(mx, __shfl_xor_sync(0xffffffffu, mx, o));
    a.x = __expf(a.x - mx); a.y = __expf(a.y - mx); a.z = __expf(a.z - mx); a.w = __expf(a.w - mx);
    b.x = __expf(b.x - mx); b.y = __expf(b.y - mx); b.z = __expf(b.z - mx); b.w = __expf(b.w - mx);
    float sm = a.x + a.y + a.z + a.w + b.x + b.y + b.z + b.w;
    #pragma unroll
    for (int o = 16; o > 0; o >>= 1) sm += __shfl_xor_sync(0xffffffffu, sm, o);
    float inv = 1.f / sm;
    __half2* hp = (__half2*)(P + row * 256);
    hp[2 * lane]          = __floats2half2_rn(a.x * inv, a.y * inv);
    hp[2 * lane + 1]      = __floats2half2_rn(a.z * inv, a.w * inv);
    hp[64 + 2 * lane]     = __floats2half2_rn(b.x * inv, b.y * inv);
    hp[64 + 2 * lane + 1] = __floats2half2_rn(b.z * inv, b.w * inv);
}

// ---------------- split-K reduce + bias + residual (+LN on residual) + stats ----
template<int PPART, int LNRES, int OFF>
__global__ void redres_k(const float* __restrict__ parts, const float* __restrict__ bias,
                         const float* __restrict__ R, float* __restrict__ X,
                         const float* __restrict__ lnw, const float* __restrict__ lnb) {
    __shared__ float shr[2][8];
    int gid = blockIdx.x * 256 + threadIdx.x;       // float4 index < 65536
    int bt = gid >> 14;
    float lnm = 0.f, lnri = 0.f;
    if (LNRES) {
        lnm = g_red[bt * 2] * (1.f / 65536.f);
        float var = g_red[bt * 2 + 1] * (1.f / 65536.f) - lnm * lnm;
        lnri = rsqrtf(var + 1e-5f);
    }
    const float4* pp = (const float4*)parts;
    float4 a = pp[gid];
    #pragma unroll
    for (int p = 1; p < PPART; p++) {
        float4 v = pp[gid + p * (TOT / 4)];
        a.x += v.x; a.y += v.y; a.z += v.z; a.w += v.w;
    }
    float4 bv = ((const float4*)bias)[gid & 63];
    float4 rv = ((const float4*)R)[gid];
    if (LNRES) {
        int p = gid & 16383;
        float4 wv = ((const float4*)lnw)[p];
        float4 lv = ((const float4*)lnb)[p];
        rv.x = (rv.x - lnm) * lnri * wv.x + lv.x;
        rv.y = (rv.y - lnm) * lnri * wv.y + lv.y;
        rv.z = (rv.z - lnm) * lnri * wv.z + lv.z;
        rv.w = (rv.w - lnm) * lnri * wv.w + lv.w;
    }
    a.x += bv.x + rv.x; a.y += bv.y + rv.y; a.z += bv.z + rv.z; a.w += bv.w + rv.w;
    ((float4*)X)[gid] = a;
    float s = a.x + a.y + a.z + a.w;
    float q = a.x * a.x + a.y * a.y + a.z * a.z + a.w * a.w;
    #pragma unroll
    for (int o = 16; o > 0; o >>= 1) {
        s += __shfl_xor_sync(0xffffffffu, s, o);
        q += __shfl_xor_sync(0xffffffffu, q, o);
    }
    int lane = threadIdx.x & 31, wp = threadIdx.x >> 5;
    if (lane == 0) { shr[0][wp] = s; shr[1][wp] = q; }
    __syncthreads();
    if (threadIdx.x == 0) {
        float ts = 0.f, tq = 0.f;
        #pragma unroll
        for (int i = 0; i < 8; i++) { ts += shr[0][i]; tq += shr[1][i]; }
        atomicAdd(&g_red[OFF + bt * 2], ts);
        atomicAdd(&g_red[OFF + bt * 2 + 1], tq);
    }
}

// ---------------- LayerNorm apply (final) ---------------------------------------
__global__ void ln_k(const float* __restrict__ X, const float* __restrict__ w,
                     const float* __restrict__ b, float* __restrict__ out) {
    int gid = blockIdx.x * blockDim.x + threadIdx.x;   // < 65536 float4s
    int bt = gid >> 14;
    float m   = g_red[8 + bt * 2] * (1.f / 65536.f);
    float var = g_red[8 + bt * 2 + 1] * (1.f / 65536.f) - m * m;
    float ri  = rsqrtf(var + 1e-5f);
    int p = gid & 16383;
    float4 x  = ((const float4*)X)[gid];
    float4 wv = ((const float4*)w)[p];
    float4 bv = ((const float4*)b)[p];
    float4 o;
    o.x = (x.x - m) * ri * wv.x + bv.x;
    o.y = (x.y - m) * ri * wv.y + bv.y;
    o.z = (x.z - m) * ri * wv.z + bv.z;
    o.w = (x.w - m) * ri * wv.w + bv.w;
    ((float4*)out)[gid] = o;
}

// ---------------- launch ----------------------------------------------------------
extern "C" void kernel_launch(void* const* d_in, const int* in_sizes, int n_in,
                              void* d_out, int out_size) {
    const float* feat = (const float*)d_in[0];
    const float* loc  = (const float*)d_in[1];
    const float* Kw   = (const float*)d_in[2];
    const float* Kb   = (const float*)d_in[3];
    const float* Qw   = (const float*)d_in[4];
    const float* Qb   = (const float*)d_in[5];
    const float* Vw   = (const float*)d_in[6];
    const float* Vb   = (const float*)d_in[7];
    const float* Fw   = (const float*)d_in[8];
    const float* Fb   = (const float*)d_in[9];
    const float* pe1w = (const float*)d_in[10];
    const float* pe1b = (const float*)d_in[11];
    const float* pe2w = (const float*)d_in[12];
    const float* pe2b = (const float*)d_in[13];
    const float* f1w  = (const float*)d_in[14];
    const float* f1b  = (const float*)d_in[15];
    const float* f2w  = (const float*)d_in[16];
    const float* f2b  = (const float*)d_in[17];
    const float* ln1w = (const float*)d_in[18];
    const float* ln1b = (const float*)d_in[19];
    const float* ln2w = (const float*)d_in[20];
    const float* ln2b = (const float*)d_in[21];
    float* out = (float*)d_out;

    __half *pQKV, *pPsum, *pSh, *pPh, *pAvp, *pFfnh;
    float *pPart, *pRes1, *pRes2;
    cudaGetSymbolAddress((void**)&pQKV, g_QKVh);
    cudaGetSymbolAddress((void**)&pPsum, g_psumh);
    cudaGetSymbolAddress((void**)&pSh, g_Sh);
    cudaGetSymbolAddress((void**)&pPh, g_Ph);
    cudaGetSymbolAddress((void**)&pAvp, g_avph);
    cudaGetSymbolAddress((void**)&pFfnh, g_ffnh);
    cudaGetSymbolAddress((void**)&pPart, g_part);
    cudaGetSymbolAddress((void**)&pRes1, g_res1);
    cudaGetSymbolAddress((void**)&pRes2, g_res2);

    static cudaStream_t sPE = nullptr, sV = nullptr;
    static cudaEvent_t evFork = nullptr, evJoin = nullptr, evV = nullptr;
    if (sPE == nullptr) {
        cudaStreamCreateWithFlags(&sPE, cudaStreamNonBlocking);
        cudaStreamCreateWithFlags(&sV, cudaStreamNonBlocking);
        cudaEventCreateWithFlags(&evFork, cudaEventDisableTiming);
        cudaEventCreateWithFlags(&evJoin, cudaEventDisableTiming);
        cudaEventCreateWithFlags(&evV, cudaEventDisableTiming);
    }

    // ---- fork ----
    cudaEventRecord(evFork, 0);
    cudaStreamWaitEvent(sPE, evFork, 0);
    cudaStreamWaitEvent(sV, evFork, 0);

    // PE branch
    prep_k<<<1, 128, 0, sPE>>>(pe2w, pe2b);
    pe_k<<<512, 256, 0, sPE>>>(loc, pe1w, pe1b);
    cudaEventRecord(evJoin, sPE);

    // V projection branch: [1024,256] @ Vw -> QKVh cols [512,768)
    gtc<64, 0, EPI_BIAS, 0, 4, 0, 0, 1, 0, 0><<<dim3(4, 16, 1), 128, 0, sV>>>(
        feat, nullptr, Vw, nullptr, nullptr, Vb, nullptr, nullptr,
        pQKV + 512, nullptr, nullptr,
        256, 256, 256, 768, 0, 0, 0, 0, 0, 0, 0);
    cudaEventRecord(evV, sV);

    // ---- main branch ----
    // QK: [1024,256] @ {Qw|Kw} -> QKVh cols [0,512), BM=64, grid 128
    gtc<64, 0, EPI_BIAS, 0, 8, 0, 0, 1, 0, 1><<<dim3(8, 16, 1), 128>>>(
        feat, nullptr, Qw, Kw, nullptr, Qb, Kb, nullptr,
        pQKV, nullptr, nullptr,
        256, 256, 256, 768, 0, 0, 0, 0, 0, 0, 0);

    // scores: per (b,h) K-rows · Q-rows^T * 0.125 -> Sh (half), grid 512
    gtc<32, 1, EPI_SCL, 0, 4, 1, 1, 1, 0, 0><<<dim3(4, 8, 16), 128>>>(
        pQKV + 256, nullptr, pQKV, nullptr, nullptr, nullptr, nullptr, nullptr,
        pSh, nullptr, nullptr,
        64, 768, 768, 256, 196608, 64, 196608, 64, 262144, 65536, 0);

    // join PE, then softmax (adds 0.125*psum)
    cudaStreamWaitEvent(0, evJoin, 0);
    softmax_k<<<512, 256>>>(pSh, pPsum, pPh);

    // join V, then AV: attn(half) @ V(half), split-K 2 (BM=32, grid 256)
    cudaStreamWaitEvent(0, evV, 0);
    gtc<32, 0, EPI_NONE, 0, 1, 1, 1, 1, 0, 0><<<dim3(2, 8, 16), 128>>>(
        pPh, nullptr, pQKV + 512, nullptr, nullptr, nullptr, nullptr, nullptr,
        pAvp, nullptr, nullptr,
        128, 256, 768, 256, 262144, 65536, 196608, 64, 65536, 64, TOT);

    // output projection: A = avp0+avp1 (half), split-K 2 -> part fp32
    gtc<64, 0, EPI_NONE, 1, 4, 1, 0, 0, 0, 0><<<dim3(8, 16, 1), 128>>>(
        pAvp, pAvp + TOT, Fw, nullptr, nullptr, nullptr, nullptr, nullptr,
        pPart, nullptr, nullptr,
        128, 256, 256, 256, 0, 0, 0, 0, 0, 0, TOT);

    // reduce + Fb + feat residual -> res1, LN1 stats -> red[0..7]
    redres_k<2, 0, 0><<<256, 256>>>(pPart, Fb, feat, pRes1, nullptr, nullptr);

    // FFN1: A = LN1(res1) on load; bias+relu -> ffnh (half)
    gtc<64, 0, EPI_BRELU, 0, 16, 0, 0, 1, 1, 0><<<dim3(16, 16, 1), 128>>>(
        pRes1, nullptr, f1w, nullptr, nullptr, f1b, nullptr, nullptr,
        pFfnh, ln1w, ln1b,
        256, 256, 1024, 1024, 0, 0, 0, 0, 0, 0, 0);

    // FFN2: A = ffnh (half), split-K 4 -> part fp32
    gtc<64, 0, EPI_NONE, 0, 4, 1, 0, 0, 0, 0><<<dim3(16, 16, 1), 128>>>(
        pFfnh, nullptr, f2w, nullptr, nullptr, nullptr, nullptr, nullptr,
        pPart, nullptr, nullptr,
        256, 1024, 256, 256, 0, 0, 0, 0, 0, 0, TOT);

    // reduce + f2b + LN1(res1) residual -> res2, LN2 stats -> red[8..15]
    redres_k<4, 1, 8><<<256, 256>>>(pPart, f2b, pRes1, pRes2, ln1w, ln1b);

    // final LN2 -> out
    ln_k<<<256, 256>>>(pRes2, ln2w, ln2b, out);
}

// round 16
// speedup vs baseline: 1.0649x; 1.0217x over previous
#include <cuda_runtime.h>
#include <cuda_fp16.h>

#define PLANE  65536
#define TOT    262144

typedef unsigned long long ull;

__device__ __forceinline__ ull pk2(float x, float y) {
    ull r; asm("mov.b64 %0, {%1,%2};" : "=l"(r) : "f"(x), "f"(y)); return r;
}
__device__ __forceinline__ void upk2(ull v, float& x, float& y) {
    asm("mov.b64 {%0,%1}, %2;" : "=f"(x), "=f"(y) : "l"(v));
}
__device__ __forceinline__ ull ffma2(ull a, ull b, ull c) {
    ull d; asm("fma.rn.f32x2 %0, %1, %2, %3;" : "=l"(d) : "l"(a), "l"(b), "l"(c)); return d;
}
__device__ __forceinline__ unsigned f2t(float x) {
    unsigned u; asm("cvt.rna.tf32.f32 %0, %1;" : "=r"(u) : "f"(x)); return u;
}
__device__ __forceinline__ void mma8(float* d,
                                     unsigned a0, unsigned a1, unsigned a2, unsigned a3,
                                     unsigned b0, unsigned b1) {
    asm volatile("mma.sync.aligned.m16n8k8.row.col.f32.tf32.tf32.f32 "
                 "{%0,%1,%2,%3}, {%4,%5,%6,%7}, {%8,%9}, {%0,%1,%2,%3};"
                 : "+f"(d[0]), "+f"(d[1]), "+f"(d[2]), "+f"(d[3])
                 : "r"(a0), "r"(a1), "r"(a2), "r"(a3), "r"(b0), "r"(b1));
}

template<int H>
__device__ __forceinline__ float4 ldvec(const void* base, long elem) {
    if (H) {
        const __half* hp = (const __half*)base + elem;
        uint2 u = *(const uint2*)hp;
        __half2 h0 = *reinterpret_cast<__half2*>(&u.x);
        __half2 h1 = *reinterpret_cast<__half2*>(&u.y);
        float2 f0 = __half22float2(h0), f1 = __half22float2(h1);
        return make_float4(f0.x, f0.y, f1.x, f1.y);
    } else {
        return *(const float4*)((const float*)base + elem);
    }
}
template<int H>
__device__ __forceinline__ void st2v(void* base, long elem, float x, float y) {
    if (H) *(__half2*)((__half*)base + elem) = __floats2half2_rn(x, y);
    else   *(float2*)((float*)base + elem) = make_float2(x, y);
}

// ---------------- scratch ------------------------------------------------------
__device__ __half g_QKVh[1024 * 768];
__device__ __half g_psumh[16 * PLANE];
__device__ __half g_Sh[16 * PLANE];
__device__ __half g_Ph[16 * PLANE];
__device__ __half g_avph[2 * TOT];
__device__ float  g_part[4 * TOT];
__device__ float  g_res1[TOT];
__device__ float  g_res2[TOT];
__device__ __half g_ffnh[1024 * 1024];
__device__ float  g_pe2s[128 * 4];
__device__ float  g_pe2bs[4];
__device__ float  g_red[16];

// ---------------- prep: fold pe2, zero LN accumulators -------------------------
__global__ void prep_k(const float* __restrict__ pe2w, const float* __restrict__ pe2b) {
    int tid = threadIdx.x;  // 128 threads
    #pragma unroll
    for (int h = 0; h < 4; h++) {
        float s = 0.f;
        #pragma unroll 8
        for (int c = 0; c < 64; c++) s += pe2w[tid * 256 + h * 64 + c];
        g_pe2s[tid * 4 + h] = s;
    }
    if (tid < 4) {
        float s = 0.f;
        for (int c = 0; c < 64; c++) s += pe2b[tid * 64 + c];
        g_pe2bs[tid] = s;
    }
    if (tid < 16) g_red[tid] = 0.f;
}

// ---------------- PE MLP (folded), 2 rows/thread, f32x2, fp16 out --------------
__global__ void pe_k(const float* __restrict__ loc, const float* __restrict__ w1,
                     const float* __restrict__ b1) {
    __shared__ float4 sW[128];
    __shared__ ull    sS[128][4];
    __shared__ float  sB[4];
    int tid = threadIdx.x;
    if (tid < 128) {
        sW[tid] = make_float4(b1[tid], w1[tid], w1[128 + tid], w1[256 + tid]);
        float4 sv = *(const float4*)(g_pe2s + tid * 4);
        sS[tid][0] = pk2(sv.x, sv.x);
        sS[tid][1] = pk2(sv.y, sv.y);
        sS[tid][2] = pk2(sv.z, sv.z);
        sS[tid][3] = pk2(sv.w, sv.w);
    }
    if (tid < 4) sB[tid] = g_pe2bs[tid];
    __syncthreads();

    int gid = blockIdx.x * 256 + tid;       // < 131072, 2 rows each
    const float2* L = (const float2*)loc;
    float2 l0 = L[3 * gid], l1 = L[3 * gid + 1], l2 = L[3 * gid + 2];
    ull A0 = pk2(sB[0], sB[0]), A1 = pk2(sB[1], sB[1]);
    ull A2 = pk2(sB[2], sB[2]), A3 = pk2(sB[3], sB[3]);
    #pragma unroll 4
    for (int i = 0; i < 128; i++) {
        float4 w = sW[i];
        float h0 = fmaf(l1.x, w.w, fmaf(l0.y, w.z, fmaf(l0.x, w.y, w.x)));
        float h1 = fmaf(l2.y, w.w, fmaf(l2.x, w.z, fmaf(l1.y, w.y, w.x)));
        h0 = fmaxf(h0, 0.f); h1 = fmaxf(h1, 0.f);
        ull hd = pk2(h0, h1);
        A0 = ffma2(hd, sS[i][0], A0);
        A1 = ffma2(hd, sS[i][1], A1);
        A2 = ffma2(hd, sS[i][2], A2);
        A3 = ffma2(hd, sS[i][3], A3);
    }
    int r0 = 2 * gid;
    int b = r0 >> 16, m = (r0 >> 8) & 255, k2 = (r0 & 255) >> 1;
    __half2* P = (__half2*)g_psumh;
    long base = ((long)b * 4) * 32768 + (long)m * 128 + k2;
    float x, y;
    upk2(A0, x, y); P[base]             = __floats2half2_rn(x, y);
    upk2(A1, x, y); P[base + 32768]     = __floats2half2_rn(x, y);
    upk2(A2, x, y); P[base + 2 * 32768] = __floats2half2_rn(x, y);
    upk2(A3, x, y); P[base + 3 * 32768] = __floats2half2_rn(x, y);
}

// ---------------- TF32 GEMM: BM in {32,64}, BN=64, BK=32, 128 thr ---------------
#define EPI_NONE  0
#define EPI_BIAS  1
#define EPI_BRELU 2
#define EPI_SCL   3

template<int BM, int TRB, int EPI, int ASUM, int NBL, int AH, int BH, int CH, int LNA, int SRC3>
__global__ void gtc(const void* __restrict__ A, const void* __restrict__ A2,
                    const void* __restrict__ Bp0, const void* __restrict__ Bp1,
                    const void* __restrict__ Bp2,
                    const float* __restrict__ bias0, const float* __restrict__ bias1,
                    const float* __restrict__ bias2,
                    void* __restrict__ C,
                    const float* __restrict__ lnw, const float* __restrict__ lnb,
                    int KSPL, int lda, int ldb, int ldc,
                    long sAb, long sAh, long sBb, long sBh, long sCb, long sCh,
                    long spC) {
    constexpr int BN = 64, BK = 32, NTHR = 128;
    constexpr int MI = BM / 32;
    constexpr int APT = BM / 16;
    constexpr int BPT = 4;
    __shared__ unsigned As[2][BK][BM + 8];
    __shared__ unsigned Bs[2][BK][72];

    int tid = threadIdx.x, w = tid >> 5, lane = tid & 31;
    int g = lane >> 2, t = lane & 3;
    int wr = w & 1, wc = w >> 1;
    int nb = blockIdx.x % NBL, sp = blockIdx.x / NBL;
    int z = blockIdx.z, zb = z >> 2, zh = z & 3;
    long kb0 = (long)sp * KSPL;

    const void* Bsel = Bp0;
    const float* bias = bias0;
    int bcol0;
    if (SRC3) {
        int sel = blockIdx.x >> 2;
        Bsel = (sel == 0) ? Bp0 : (sel == 1 ? Bp1 : Bp2);
        bias = (sel == 0) ? bias0 : (sel == 1 ? bias1 : bias2);
        bcol0 = (blockIdx.x & 3) * BN;
    } else {
        bcol0 = nb * BN;
    }

    long aBase = zb * sAb + zh * sAh + (long)(blockIdx.y * BM) * lda + kb0;
    long bBase;
    if (TRB) bBase = zb * sBb + zh * sBh + (long)(nb * BN) * ldb + kb0;
    else     bBase = zb * sBb + zh * sBh + kb0 * (long)ldb + bcol0;

    int bat = (blockIdx.y * BM) >> 8;
    float lnm = 0.f, lnri = 0.f;
    if (LNA) {
        lnm = g_red[bat * 2] * (1.f / 65536.f);
        float var = g_red[bat * 2 + 1] * (1.f / 65536.f) - lnm * lnm;
        lnri = rsqrtf(var + 1e-5f);
    }

    int aR[APT], aC[APT], bR[BPT], bC[BPT];
    #pragma unroll
    for (int i = 0; i < APT; i++) {
        int s = tid + i * NTHR;
        aR[i] = s >> 3; aC[i] = (s & 7) * 4;
    }
    #pragma unroll
    for (int i = 0; i < BPT; i++) {
        int s = tid + i * NTHR;
        if (TRB) { bR[i] = s >> 3; bC[i] = (s & 7) * 4; }
        else     { bR[i] = s >> 4; bC[i] = (s & 15) * 4; }
    }
    float4 rA[APT], rB[BPT];

    auto ldg = [&](int kt) {
        int kb = kt * BK;
        #pragma unroll
        for (int i = 0; i < APT; i++) {
            long off = aBase + (long)aR[i] * lda + kb + aC[i];
            float4 v = ldvec<AH>(A, off);
            if (ASUM) {
                float4 v2 = ldvec<AH>(A2, off);
                v.x += v2.x; v.y += v2.y; v.z += v2.z; v.w += v2.w;
            }
            if (LNA) {
                int p = (int)(((long)(blockIdx.y * BM + aR[i]) * lda + kb + aC[i]) & 65535);
                float4 wv = *(const float4*)(lnw + p);
                float4 bv = *(const float4*)(lnb + p);
                v.x = (v.x - lnm) * lnri * wv.x + bv.x;
                v.y = (v.y - lnm) * lnri * wv.y + bv.y;
                v.z = (v.z - lnm) * lnri * wv.z + bv.z;
                v.w = (v.w - lnm) * lnri * wv.w + bv.w;
            }
            rA[i] = v;
        }
        #pragma unroll
        for (int i = 0; i < BPT; i++) {
            long off;
            if (TRB) off = bBase + (long)bR[i] * ldb + kb + bC[i];
            else     off = bBase + (long)(kb + bR[i]) * ldb + bC[i];
            rB[i] = ldvec<BH>(Bsel, off);
        }
    };
    auto sts = [&](int bf) {
        #pragma unroll
        for (int i = 0; i < APT; i++) {
            float4 v = rA[i];
            As[bf][aC[i] + 0][aR[i]] = f2t(v.x);
            As[bf][aC[i] + 1][aR[i]] = f2t(v.y);
            As[bf][aC[i] + 2][aR[i]] = f2t(v.z);
            As[bf][aC[i] + 3][aR[i]] = f2t(v.w);
        }
        #pragma unroll
        for (int i = 0; i < BPT; i++) {
            float4 v = rB[i];
            if (TRB) {
                Bs[bf][bC[i] + 0][bR[i]] = f2t(v.x);
                Bs[bf][bC[i] + 1][bR[i]] = f2t(v.y);
                Bs[bf][bC[i] + 2][bR[i]] = f2t(v.z);
                Bs[bf][bC[i] + 3][bR[i]] = f2t(v.w);
            } else {
                *(uint4*)&Bs[bf][bR[i]][bC[i]] =
                    make_uint4(f2t(v.x), f2t(v.y), f2t(v.z), f2t(v.w));
            }
        }
    };

    float acc[MI][4][4] = {};
    int wm = wr * (MI * 16), wn = wc * 32;
    int KT = KSPL / BK, buf = 0;

    ldg(0); sts(0); __syncthreads();
    for (int kt = 0; kt < KT; kt++) {
        if (kt + 1 < KT) ldg(kt + 1);
        #pragma unroll
        for (int ks = 0; ks < BK / 8; ks++) {
            unsigned af[MI][4], bfr[4][2];
            #pragma unroll
            for (int mi = 0; mi < MI; mi++) {
                int m0 = wm + mi * 16 + g;
                af[mi][0] = As[buf][ks * 8 + t][m0];
                af[mi][1] = As[buf][ks * 8 + t][m0 + 8];
                af[mi][2] = As[buf][ks * 8 + t + 4][m0];
                af[mi][3] = As[buf][ks * 8 + t + 4][m0 + 8];
            }
            #pragma unroll
            for (int ni = 0; ni < 4; ni++) {
                int n0 = wn + ni * 8 + g;
                bfr[ni][0] = Bs[buf][ks * 8 + t][n0];
                bfr[ni][1] = Bs[buf][ks * 8 + t + 4][n0];
            }
            #pragma unroll
            for (int mi = 0; mi < MI; mi++)
                #pragma unroll
                for (int ni = 0; ni < 4; ni++)
                    mma8(acc[mi][ni], af[mi][0], af[mi][1], af[mi][2], af[mi][3],
                         bfr[ni][0], bfr[ni][1]);
        }
        if (kt + 1 < KT) { sts(buf ^ 1); __syncthreads(); buf ^= 1; }
    }

    long Cb = zb * sCb + zh * sCh + (long)sp * spC;
    int row0 = blockIdx.y * BM + wm;
    int ocol0 = (SRC3 ? blockIdx.x * BN : nb * BN) + wn;
    int bcolw = bcol0 + wn;
    #pragma unroll
    for (int mi = 0; mi < MI; mi++) {
        #pragma unroll
        for (int ni = 0; ni < 4; ni++) {
            int cl = ni * 8 + 2 * t;
            #pragma unroll
            for (int half = 0; half < 2; half++) {
                int r = row0 + mi * 16 + g + half * 8;
                float x = acc[mi][ni][half * 2], y = acc[mi][ni][half * 2 + 1];
                long idx = Cb + (long)r * ldc + ocol0 + cl;
                if (EPI == EPI_BIAS || EPI == EPI_BRELU) {
                    float2 bv = *(const float2*)(bias + bcolw + cl);
                    x += bv.x; y += bv.y;
                    if (EPI == EPI_BRELU) { x = fmaxf(x, 0.f); y = fmaxf(y, 0.f); }
                }
                if (EPI == EPI_SCL) { x *= 0.125f; y *= 0.125f; }
                st2v<CH>(C, idx, x, y);
            }
        }
    }
}

// ---------------- softmax: arg = S(half) + 0.125*psum(half); fp16 probs --------
__global__ void softmax_k(const __half* __restrict__ S, const __half* __restrict__ psum,
                          __half* __restrict__ P) {
    int t = threadIdx.x, warp = t >> 5, lane = t & 31;
    long row = (long)blockIdx.x * 8 + warp;
    const __half2* sp = (const __half2*)(S + row * 256);
    const __half2* pp = (const __half2*)(psum + row * 256);
    float2 s0 = __half22float2(sp[2 * lane]);
    float2 s1 = __half22float2(sp[2 * lane + 1]);
    float2 s2 = __half22float2(sp[64 + 2 * lane]);
    float2 s3 = __half22float2(sp[64 + 2 * lane + 1]);
    float2 p0 = __half22float2(pp[2 * lane]);
    float2 p1 = __half22float2(pp[2 * lane + 1]);
    float2 p2 = __half22float2(pp[64 + 2 * lane]);
    float2 p3 = __half22float2(pp[64 + 2 * lane + 1]);
    float4 a = make_float4(s0.x + 0.125f * p0.x, s0.y + 0.125f * p0.y,
                           s1.x + 0.125f * p1.x, s1.y + 0.125f * p1.y);
    float4 b = make_float4(s2.x + 0.125f * p2.x, s2.y + 0.125f * p2.y,
                           s3.x + 0.125f * p3.x, s3.y + 0.125f * p3.y);
    float mx = fmaxf(fmaxf(fmaxf(a.x, a.y), fmaxf(a.z, a.w)),
                     fmaxf(fmaxf(b.x, b.y), fmaxf(b.z, b.w)));
    #pragma unroll
    for (int o = 16; o > 0; o >>= 1) mx = fmaxf(mx, __shfl_xor_sync(0xffffffffu, mx, o));
    a.x = __expf(a.x - mx); a.y = __expf(a.y - mx); a.z = __expf(a.z - mx); a.w = __expf(a.w - mx);
    b.x = __expf(b.x - mx); b.y = __expf(b.y - mx); b.z = __expf(b.z - mx); b.w = __expf(b.w - mx);
    float sm = a.x + a.y + a.z + a.w + b.x + b.y + b.z + b.w;
    #pragma unroll
    for (int o = 16; o > 0; o >>= 1) sm += __shfl_xor_sync(0xffffffffu, sm, o);
    float inv = 1.f / sm;
    __half2* hp = (__half2*)(P + row * 256);
    hp[2 * lane]          = __floats2half2_rn(a.x * inv, a.y * inv);
    hp[2 * lane + 1]      = __floats2half2_rn(a.z * inv, a.w * inv);
    hp[64 + 2 * lane]     = __floats2half2_rn(b.x * inv, b.y * inv);
    hp[64 + 2 * lane + 1] = __floats2half2_rn(b.z * inv, b.w * inv);
}

// ---------------- split-K reduce + bias + residual (+LN on residual) + stats ----
template<int PPART, int LNRES, int OFF>
__global__ void redres_k(const float* __restrict__ parts, const float* __restrict__ bias,
                         const float* __restrict__ R, float* __restrict__ X,
                         const float* __restrict__ lnw, const float* __restrict__ lnb) {
    __shared__ float shr[2][8];
    int gid = blockIdx.x * 256 + threadIdx.x;       // float4 index < 65536
    int bt = gid >> 14;
    float lnm = 0.f, lnri = 0.f;
    if (LNRES) {
        lnm = g_red[bt * 2] * (1.f / 65536.f);
        float var = g_red[bt * 2 + 1] * (1.f / 65536.f) - lnm * lnm;
        lnri = rsqrtf(var + 1e-5f);
    }
    const float4* pp = (const float4*)parts;
    float4 a = pp[gid];
    #pragma unroll
    for (int p = 1; p < PPART; p++) {
        float4 v = pp[gid + p * (TOT / 4)];
        a.x += v.x; a.y += v.y; a.z += v.z; a.w += v.w;
    }
    float4 bv = ((const float4*)bias)[gid & 63];
    float4 rv = ((const float4*)R)[gid];
    if (LNRES) {
        int p = gid & 16383;
        float4 wv = ((const float4*)lnw)[p];
        float4 lv = ((const float4*)lnb)[p];
        rv.x = (rv.x - lnm) * lnri * wv.x + lv.x;
        rv.y = (rv.y - lnm) * lnri * wv.y + lv.y;
        rv.z = (rv.z - lnm) * lnri * wv.z + lv.z;
        rv.w = (rv.w - lnm) * lnri * wv.w + lv.w;
    }
    a.x += bv.x + rv.x; a.y += bv.y + rv.y; a.z += bv.z + rv.z; a.w += bv.w + rv.w;
    ((float4*)X)[gid] = a;
    float s = a.x + a.y + a.z + a.w;
    float q = a.x * a.x + a.y * a.y + a.z * a.z + a.w * a.w;
    #pragma unroll
    for (int o = 16; o > 0; o >>= 1) {
        s += __shfl_xor_sync(0xffffffffu, s, o);
        q += __shfl_xor_sync(0xffffffffu, q, o);
    }
    int lane = threadIdx.x & 31, wp = threadIdx.x >> 5;
    if (lane == 0) { shr[0][wp] = s; shr[1][wp] = q; }
    __syncthreads();
    if (threadIdx.x == 0) {
        float ts = 0.f, tq = 0.f;
        #pragma unroll
        for (int i = 0; i < 8; i++) { ts += shr[0][i]; tq += shr[1][i]; }
        atomicAdd(&g_red[OFF + bt * 2], ts);
        atomicAdd(&g_red[OFF + bt * 2 + 1], tq);
    }
}

// ---------------- LayerNorm apply (final) ---------------------------------------
__global__ void ln_k(const float* __restrict__ X, const float* __restrict__ w,
                     const float* __restrict__ b, float* __restrict__ out) {
    int gid = blockIdx.x * blockDim.x + threadIdx.x;   // < 65536 float4s
    int bt = gid >> 14;
    float m   = g_red[8 + bt * 2] * (1.f / 65536.f);
    float var = g_red[8 + bt * 2 + 1] * (1.f / 65536.f) - m * m;
    float ri  = rsqrtf(var + 1e-5f);
    int p = gid & 16383;
    float4 x  = ((const float4*)X)[gid];
    float4 wv = ((const float4*)w)[p];
    float4 bv = ((const float4*)b)[p];
    float4 o;
    o.x = (x.x - m) * ri * wv.x + bv.x;
    o.y = (x.y - m) * ri * wv.y + bv.y;
    o.z = (x.z - m) * ri * wv.z + bv.z;
    o.w = (x.w - m) * ri * wv.w + bv.w;
    ((float4*)out)[gid] = o;
}

// ---------------- launch ----------------------------------------------------------
extern "C" void kernel_launch(void* const* d_in, const int* in_sizes, int n_in,
                              void* d_out, int out_size) {
    const float* feat = (const float*)d_in[0];
    const float* loc  = (const float*)d_in[1];
    const float* Kw   = (const float*)d_in[2];
    const float* Kb   = (const float*)d_in[3];
    const float* Qw   = (const float*)d_in[4];
    const float* Qb   = (const float*)d_in[5];
    const float* Vw   = (const float*)d_in[6];
    const float* Vb   = (const float*)d_in[7];
    const float* Fw   = (const float*)d_in[8];
    const float* Fb   = (const float*)d_in[9];
    const float* pe1w = (const float*)d_in[10];
    const float* pe1b = (const float*)d_in[11];
    const float* pe2w = (const float*)d_in[12];
    const float* pe2b = (const float*)d_in[13];
    const float* f1w  = (const float*)d_in[14];
    const float* f1b  = (const float*)d_in[15];
    const float* f2w  = (const float*)d_in[16];
    const float* f2b  = (const float*)d_in[17];
    const float* ln1w = (const float*)d_in[18];
    const float* ln1b = (const float*)d_in[19];
    const float* ln2w = (const float*)d_in[20];
    const float* ln2b = (const float*)d_in[21];
    float* out = (float*)d_out;

    __half *pQKV, *pPsum, *pSh, *pPh, *pAvp, *pFfnh;
    float *pPart, *pRes1, *pRes2;
    cudaGetSymbolAddress((void**)&pQKV, g_QKVh);
    cudaGetSymbolAddress((void**)&pPsum, g_psumh);
    cudaGetSymbolAddress((void**)&pSh, g_Sh);
    cudaGetSymbolAddress((void**)&pPh, g_Ph);
    cudaGetSymbolAddress((void**)&pAvp, g_avph);
    cudaGetSymbolAddress((void**)&pFfnh, g_ffnh);
    cudaGetSymbolAddress((void**)&pPart, g_part);
    cudaGetSymbolAddress((void**)&pRes1, g_res1);
    cudaGetSymbolAddress((void**)&pRes2, g_res2);

    static cudaStream_t sPE = nullptr, sV = nullptr;
    static cudaEvent_t evFork = nullptr, evJoin = nullptr, evV = nullptr;
    if (sPE == nullptr) {
        int lo = 0, hi = 0;
        cudaDeviceGetStreamPriorityRange(&lo, &hi);   // lo = lowest priority
        cudaStreamCreateWithPriority(&sPE, cudaStreamNonBlocking, lo);
        cudaStreamCreateWithPriority(&sV, cudaStreamNonBlocking, lo);
        cudaEventCreateWithFlags(&evFork, cudaEventDisableTiming);
        cudaEventCreateWithFlags(&evJoin, cudaEventDisableTiming);
        cudaEventCreateWithFlags(&evV, cudaEventDisableTiming);
    }

    // ---- fork ----
    cudaEventRecord(evFork, 0);
    cudaStreamWaitEvent(sPE, evFork, 0);
    cudaStreamWaitEvent(sV, evFork, 0);

    // PE branch (low priority; backfills SMs once QK's 128 blocks are placed)
    prep_k<<<1, 128, 0, sPE>>>(pe2w, pe2b);
    pe_k<<<512, 256, 0, sPE>>>(loc, pe1w, pe1b);
    cudaEventRecord(evJoin, sPE);

    // V projection branch (low priority): [1024,256] @ Vw -> QKVh cols [512,768)
    gtc<64, 0, EPI_BIAS, 0, 4, 0, 0, 1, 0, 0><<<dim3(4, 16, 1), 128, 0, sV>>>(
        feat, nullptr, Vw, nullptr, nullptr, Vb, nullptr, nullptr,
        pQKV + 512, nullptr, nullptr,
        256, 256, 256, 768, 0, 0, 0, 0, 0, 0, 0);
    cudaEventRecord(evV, sV);

    // ---- main branch ----
    // QK: [1024,256] @ {Qw|Kw} -> QKVh cols [0,512), BM=64, grid 128
    gtc<64, 0, EPI_BIAS, 0, 8, 0, 0, 1, 0, 1><<<dim3(8, 16, 1), 128>>>(
        feat, nullptr, Qw, Kw, nullptr, Qb, Kb, nullptr,
        pQKV, nullptr, nullptr,
        256, 256, 256, 768, 0, 0, 0, 0, 0, 0, 0);

    // scores: per (b,h) K-rows · Q-rows^T * 0.125 -> Sh (half), grid 512
    gtc<32, 1, EPI_SCL, 0, 4, 1, 1, 1, 0, 0><<<dim3(4, 8, 16), 128>>>(
        pQKV + 256, nullptr, pQKV, nullptr, nullptr, nullptr, nullptr, nullptr,
        pSh, nullptr, nullptr,
        64, 768, 768, 256, 196608, 64, 196608, 64, 262144, 65536, 0);

    // join PE, then softmax (adds 0.125*psum)
    cudaStreamWaitEvent(0, evJoin, 0);
    softmax_k<<<512, 256>>>(pSh, pPsum, pPh);

    // join V, then AV: attn(half) @ V(half), split-K 2 (BM=32, grid 256)
    cudaStreamWaitEvent(0, evV, 0);
    gtc<32, 0, EPI_NONE, 0, 1, 1, 1, 1, 0, 0><<<dim3(2, 8, 16), 128>>>(
        pPh, nullptr, pQKV + 512, nullptr, nullptr, nullptr, nullptr, nullptr,
        pAvp, nullptr, nullptr,
        128, 256, 768, 256, 262144, 65536, 196608, 64, 65536, 64, TOT);

    // output projection: A = avp0+avp1 (half), split-K 2 -> part fp32
    gtc<64, 0, EPI_NONE, 1, 4, 1, 0, 0, 0, 0><<<dim3(8, 16, 1), 128>>>(
        pAvp, pAvp + TOT, Fw, nullptr, nullptr, nullptr, nullptr, nullptr,
        pPart, nullptr, nullptr,
        128, 256, 256, 256, 0, 0, 0, 0, 0, 0, TOT);

    // reduce + Fb + feat residual -> res1, LN1 stats -> red[0..7]
    redres_k<2, 0, 0><<<256, 256>>>(pPart, Fb, feat, pRes1, nullptr, nullptr);

    // FFN1: A = LN1(res1) on load; bias+relu -> ffnh (half)
    gtc<64, 0, EPI_BRELU, 0, 16, 0, 0, 1, 1, 0><<<dim3(16, 16, 1), 128>>>(
        pRes1, nullptr, f1w, nullptr, nullptr, f1b, nullptr, nullptr,
        pFfnh, ln1w, ln1b,
        256, 256, 1024, 1024, 0, 0, 0, 0, 0, 0, 0);

    // FFN2: A = ffnh (half), split-K 4 -> part fp32
    gtc<64, 0, EPI_NONE, 0, 4, 1, 0, 0, 0, 0><<<dim3(16, 16, 1), 128>>>(
        pFfnh, nullptr, f2w, nullptr, nullptr, nullptr, nullptr, nullptr,
        pPart, nullptr, nullptr,
        256, 1024, 256, 256, 0, 0, 0, 0, 0, 0, TOT);

    // reduce + f2b + LN1(res1) residual -> res2, LN2 stats -> red[8..15]
    redres_k<4, 1, 8><<<256, 256>>>(pPart, f2b, pRes1, pRes2, ln1w, ln1b);

    // final LN2 -> out
    ln_k<<<256, 256>>>(pRes2, ln2w, ln2b, out);
}

// round 17
// speedup vs baseline: 1.0867x; 1.0205x over previous
#include <cuda_runtime.h>
#include <cuda_fp16.h>

#define PLANE  65536
#define TOT    262144

typedef unsigned long long ull;

__device__ __forceinline__ ull pk2(float x, float y) {
    ull r; asm("mov.b64 %0, {%1,%2};" : "=l"(r) : "f"(x), "f"(y)); return r;
}
__device__ __forceinline__ void upk2(ull v, float& x, float& y) {
    asm("mov.b64 {%0,%1}, %2;" : "=f"(x), "=f"(y) : "l"(v));
}
__device__ __forceinline__ ull ffma2(ull a, ull b, ull c) {
    ull d; asm("fma.rn.f32x2 %0, %1, %2, %3;" : "=l"(d) : "l"(a), "l"(b), "l"(c)); return d;
}
__device__ __forceinline__ unsigned f2t(float x) {
    unsigned u; asm("cvt.rna.tf32.f32 %0, %1;" : "=r"(u) : "f"(x)); return u;
}
__device__ __forceinline__ void mma8(float* d,
                                     unsigned a0, unsigned a1, unsigned a2, unsigned a3,
                                     unsigned b0, unsigned b1) {
    asm volatile("mma.sync.aligned.m16n8k8.row.col.f32.tf32.tf32.f32 "
                 "{%0,%1,%2,%3}, {%4,%5,%6,%7}, {%8,%9}, {%0,%1,%2,%3};"
                 : "+f"(d[0]), "+f"(d[1]), "+f"(d[2]), "+f"(d[3])
                 : "r"(a0), "r"(a1), "r"(a2), "r"(a3), "r"(b0), "r"(b1));
}

template<int H>
__device__ __forceinline__ float4 ldvec(const void* base, long elem) {
    if (H) {
        const __half* hp = (const __half*)base + elem;
        uint2 u = *(const uint2*)hp;
        __half2 h0 = *reinterpret_cast<__half2*>(&u.x);
        __half2 h1 = *reinterpret_cast<__half2*>(&u.y);
        float2 f0 = __half22float2(h0), f1 = __half22float2(h1);
        return make_float4(f0.x, f0.y, f1.x, f1.y);
    } else {
        return *(const float4*)((const float*)base + elem);
    }
}
template<int H>
__device__ __forceinline__ void st2v(void* base, long elem, float x, float y) {
    if (H) *(__half2*)((__half*)base + elem) = __floats2half2_rn(x, y);
    else   *(float2*)((float*)base + elem) = make_float2(x, y);
}

// ---------------- scratch ------------------------------------------------------
__device__ __half g_QKVh[1024 * 768];
__device__ __half g_psumh[16 * PLANE];
__device__ __half g_Sh[16 * PLANE];
__device__ __half g_avph[TOT];
__device__ float  g_part[4 * TOT];
__device__ float  g_res1[TOT];
__device__ float  g_res2[TOT];
__device__ __half g_ffnh[1024 * 1024];
__device__ float  g_pe2s[128 * 4];
__device__ float  g_pe2bs[4];
__device__ float  g_red[16];

// ---------------- prep: fold pe2, zero LN accumulators -------------------------
__global__ void prep_k(const float* __restrict__ pe2w, const float* __restrict__ pe2b) {
    int tid = threadIdx.x;  // 128 threads
    #pragma unroll
    for (int h = 0; h < 4; h++) {
        float s = 0.f;
        #pragma unroll 8
        for (int c = 0; c < 64; c++) s += pe2w[tid * 256 + h * 64 + c];
        g_pe2s[tid * 4 + h] = s;
    }
    if (tid < 4) {
        float s = 0.f;
        for (int c = 0; c < 64; c++) s += pe2b[tid * 64 + c];
        g_pe2bs[tid] = s;
    }
    if (tid < 16) g_red[tid] = 0.f;
}

// ---------------- PE MLP (folded), 2 rows/thread, f32x2, fp16 out --------------
__global__ void pe_k(const float* __restrict__ loc, const float* __restrict__ w1,
                     const float* __restrict__ b1) {
    __shared__ float4 sW[128];
    __shared__ ull    sS[128][4];
    __shared__ float  sB[4];
    int tid = threadIdx.x;
    if (tid < 128) {
        sW[tid] = make_float4(b1[tid], w1[tid], w1[128 + tid], w1[256 + tid]);
        float4 sv = *(const float4*)(g_pe2s + tid * 4);
        sS[tid][0] = pk2(sv.x, sv.x);
        sS[tid][1] = pk2(sv.y, sv.y);
        sS[tid][2] = pk2(sv.z, sv.z);
        sS[tid][3] = pk2(sv.w, sv.w);
    }
    if (tid < 4) sB[tid] = g_pe2bs[tid];
    __syncthreads();

    int gid = blockIdx.x * 256 + tid;       // < 131072, 2 rows each
    const float2* L = (const float2*)loc;
    float2 l0 = L[3 * gid], l1 = L[3 * gid + 1], l2 = L[3 * gid + 2];
    ull A0 = pk2(sB[0], sB[0]), A1 = pk2(sB[1], sB[1]);
    ull A2 = pk2(sB[2], sB[2]), A3 = pk2(sB[3], sB[3]);
    #pragma unroll 4
    for (int i = 0; i < 128; i++) {
        float4 w = sW[i];
        float h0 = fmaf(l1.x, w.w, fmaf(l0.y, w.z, fmaf(l0.x, w.y, w.x)));
        float h1 = fmaf(l2.y, w.w, fmaf(l2.x, w.z, fmaf(l1.y, w.y, w.x)));
        h0 = fmaxf(h0, 0.f); h1 = fmaxf(h1, 0.f);
        ull hd = pk2(h0, h1);
        A0 = ffma2(hd, sS[i][0], A0);
        A1 = ffma2(hd, sS[i][1], A1);
        A2 = ffma2(hd, sS[i][2], A2);
        A3 = ffma2(hd, sS[i][3], A3);
    }
    int r0 = 2 * gid;
    int b = r0 >> 16, m = (r0 >> 8) & 255, k2 = (r0 & 255) >> 1;
    __half2* P = (__half2*)g_psumh;
    long base = ((long)b * 4) * 32768 + (long)m * 128 + k2;
    float x, y;
    upk2(A0, x, y); P[base]             = __floats2half2_rn(x, y);
    upk2(A1, x, y); P[base + 32768]     = __floats2half2_rn(x, y);
    upk2(A2, x, y); P[base + 2 * 32768] = __floats2half2_rn(x, y);
    upk2(A3, x, y); P[base + 3 * 32768] = __floats2half2_rn(x, y);
}

// ---------------- TF32 GEMM: BM in {32,64}, BN=64, BK=32, 128 thr ---------------
#define EPI_NONE  0
#define EPI_BIAS  1
#define EPI_BRELU 2
#define EPI_SCL   3

template<int BM, int TRB, int EPI, int ASUM, int NBL, int AH, int BH, int CH, int LNA, int SRC3>
__global__ void gtc(const void* __restrict__ A, const void* __restrict__ A2,
                    const void* __restrict__ Bp0, const void* __restrict__ Bp1,
                    const void* __restrict__ Bp2,
                    const float* __restrict__ bias0, const float* __restrict__ bias1,
                    const float* __restrict__ bias2,
                    void* __restrict__ C,
                    const float* __restrict__ lnw, const float* __restrict__ lnb,
                    int KSPL, int lda, int ldb, int ldc,
                    long sAb, long sAh, long sBb, long sBh, long sCb, long sCh,
                    long spC) {
    constexpr int BN = 64, BK = 32, NTHR = 128;
    constexpr int MI = BM / 32;
    constexpr int APT = BM / 16;
    constexpr int BPT = 4;
    __shared__ unsigned As[2][BK][BM + 8];
    __shared__ unsigned Bs[2][BK][72];

    int tid = threadIdx.x, w = tid >> 5, lane = tid & 31;
    int g = lane >> 2, t = lane & 3;
    int wr = w & 1, wc = w >> 1;
    int nb = blockIdx.x % NBL, sp = blockIdx.x / NBL;
    int z = blockIdx.z, zb = z >> 2, zh = z & 3;
    long kb0 = (long)sp * KSPL;

    const void* Bsel = Bp0;
    const float* bias = bias0;
    int bcol0;
    if (SRC3) {
        int sel = blockIdx.x >> 2;
        Bsel = (sel == 0) ? Bp0 : (sel == 1 ? Bp1 : Bp2);
        bias = (sel == 0) ? bias0 : (sel == 1 ? bias1 : bias2);
        bcol0 = (blockIdx.x & 3) * BN;
    } else {
        bcol0 = nb * BN;
    }

    long aBase = zb * sAb + zh * sAh + (long)(blockIdx.y * BM) * lda + kb0;
    long bBase;
    if (TRB) bBase = zb * sBb + zh * sBh + (long)(nb * BN) * ldb + kb0;
    else     bBase = zb * sBb + zh * sBh + kb0 * (long)ldb + bcol0;

    int bat = (blockIdx.y * BM) >> 8;
    float lnm = 0.f, lnri = 0.f;
    if (LNA) {
        lnm = g_red[bat * 2] * (1.f / 65536.f);
        float var = g_red[bat * 2 + 1] * (1.f / 65536.f) - lnm * lnm;
        lnri = rsqrtf(var + 1e-5f);
    }

    int aR[APT], aC[APT], bR[BPT], bC[BPT];
    #pragma unroll
    for (int i = 0; i < APT; i++) {
        int s = tid + i * NTHR;
        aR[i] = s >> 3; aC[i] = (s & 7) * 4;
    }
    #pragma unroll
    for (int i = 0; i < BPT; i++) {
        int s = tid + i * NTHR;
        if (TRB) { bR[i] = s >> 3; bC[i] = (s & 7) * 4; }
        else     { bR[i] = s >> 4; bC[i] = (s & 15) * 4; }
    }
    float4 rA[APT], rB[BPT];

    auto ldg = [&](int kt) {
        int kb = kt * BK;
        #pragma unroll
        for (int i = 0; i < APT; i++) {
            long off = aBase + (long)aR[i] * lda + kb + aC[i];
            float4 v = ldvec<AH>(A, off);
            if (ASUM) {
                float4 v2 = ldvec<AH>(A2, off);
                v.x += v2.x; v.y += v2.y; v.z += v2.z; v.w += v2.w;
            }
            if (LNA) {
                int p = (int)(((long)(blockIdx.y * BM + aR[i]) * lda + kb + aC[i]) & 65535);
                float4 wv = *(const float4*)(lnw + p);
                float4 bv = *(const float4*)(lnb + p);
                v.x = (v.x - lnm) * lnri * wv.x + bv.x;
                v.y = (v.y - lnm) * lnri * wv.y + bv.y;
                v.z = (v.z - lnm) * lnri * wv.z + bv.z;
                v.w = (v.w - lnm) * lnri * wv.w + bv.w;
            }
            rA[i] = v;
        }
        #pragma unroll
        for (int i = 0; i < BPT; i++) {
            long off;
            if (TRB) off = bBase + (long)bR[i] * ldb + kb + bC[i];
            else     off = bBase + (long)(kb + bR[i]) * ldb + bC[i];
            rB[i] = ldvec<BH>(Bsel, off);
        }
    };
    auto sts = [&](int bf) {
        #pragma unroll
        for (int i = 0; i < APT; i++) {
            float4 v = rA[i];
            As[bf][aC[i] + 0][aR[i]] = f2t(v.x);
            As[bf][aC[i] + 1][aR[i]] = f2t(v.y);
            As[bf][aC[i] + 2][aR[i]] = f2t(v.z);
            As[bf][aC[i] + 3][aR[i]] = f2t(v.w);
        }
        #pragma unroll
        for (int i = 0; i < BPT; i++) {
            float4 v = rB[i];
            if (TRB) {
                Bs[bf][bC[i] + 0][bR[i]] = f2t(v.x);
                Bs[bf][bC[i] + 1][bR[i]] = f2t(v.y);
                Bs[bf][bC[i] + 2][bR[i]] = f2t(v.z);
                Bs[bf][bC[i] + 3][bR[i]] = f2t(v.w);
            } else {
                *(uint4*)&Bs[bf][bR[i]][bC[i]] =
                    make_uint4(f2t(v.x), f2t(v.y), f2t(v.z), f2t(v.w));
            }
        }
    };

    float acc[MI][4][4] = {};
    int wm = wr * (MI * 16), wn = wc * 32;
    int KT = KSPL / BK, buf = 0;

    ldg(0); sts(0); __syncthreads();
    for (int kt = 0; kt < KT; kt++) {
        if (kt + 1 < KT) ldg(kt + 1);
        #pragma unroll
        for (int ks = 0; ks < BK / 8; ks++) {
            unsigned af[MI][4], bfr[4][2];
            #pragma unroll
            for (int mi = 0; mi < MI; mi++) {
                int m0 = wm + mi * 16 + g;
                af[mi][0] = As[buf][ks * 8 + t][m0];
                af[mi][1] = As[buf][ks * 8 + t][m0 + 8];
                af[mi][2] = As[buf][ks * 8 + t + 4][m0];
                af[mi][3] = As[buf][ks * 8 + t + 4][m0 + 8];
            }
            #pragma unroll
            for (int ni = 0; ni < 4; ni++) {
                int n0 = wn + ni * 8 + g;
                bfr[ni][0] = Bs[buf][ks * 8 + t][n0];
                bfr[ni][1] = Bs[buf][ks * 8 + t + 4][n0];
            }
            #pragma unroll
            for (int mi = 0; mi < MI; mi++)
                #pragma unroll
                for (int ni = 0; ni < 4; ni++)
                    mma8(acc[mi][ni], af[mi][0], af[mi][1], af[mi][2], af[mi][3],
                         bfr[ni][0], bfr[ni][1]);
        }
        if (kt + 1 < KT) { sts(buf ^ 1); __syncthreads(); buf ^= 1; }
    }

    long Cb = zb * sCb + zh * sCh + (long)sp * spC;
    int row0 = blockIdx.y * BM + wm;
    int ocol0 = (SRC3 ? blockIdx.x * BN : nb * BN) + wn;
    int bcolw = bcol0 + wn;
    #pragma unroll
    for (int mi = 0; mi < MI; mi++) {
        #pragma unroll
        for (int ni = 0; ni < 4; ni++) {
            int cl = ni * 8 + 2 * t;
            #pragma unroll
            for (int half = 0; half < 2; half++) {
                int r = row0 + mi * 16 + g + half * 8;
                float x = acc[mi][ni][half * 2], y = acc[mi][ni][half * 2 + 1];
                long idx = Cb + (long)r * ldc + ocol0 + cl;
                if (EPI == EPI_BIAS || EPI == EPI_BRELU) {
                    float2 bv = *(const float2*)(bias + bcolw + cl);
                    x += bv.x; y += bv.y;
                    if (EPI == EPI_BRELU) { x = fmaxf(x, 0.f); y = fmaxf(y, 0.f); }
                }
                if (EPI == EPI_SCL) { x *= 0.125f; y *= 0.125f; }
                st2v<CH>(C, idx, x, y);
            }
        }
    }
}

// ---------------- fused softmax + AV ------------------------------------------
// block = (b,h, 32 score rows); 256 thr / 8 warps.
// Softmax: warp w owns rows w*4..w*4+3, lane owns 8 cols -> shfl reductions.
// Probs (tf32) -> smem; then O[32,64] = P @ V with V streamed in 8x32 chunks.
__global__ void __launch_bounds__(256) smav_k(const __half* __restrict__ Sh,
                                              const __half* __restrict__ psum,
                                              const __half* __restrict__ QKV,
                                              __half* __restrict__ merged) {
    __shared__ unsigned Ps[32][264];
    __shared__ unsigned Vs[32][72];
    int tid = threadIdx.x, w = tid >> 5, lane = tid & 31;
    int g = lane >> 2, t = lane & 3;
    int z = blockIdx.y, b = z >> 2, h = z & 3;
    int row0 = blockIdx.x * 32;
    long base = (long)z * PLANE + (long)row0 * 256;

    // ---- softmax: arg = Sh + 0.125*psum, rows of 256 ----
    #pragma unroll
    for (int rr = 0; rr < 4; rr++) {
        int r = w * 4 + rr;
        const __half2* sp = (const __half2*)(Sh + base + (long)r * 256) + lane * 4;
        const __half2* pp = (const __half2*)(psum + base + (long)r * 256) + lane * 4;
        float v[8];
        #pragma unroll
        for (int i = 0; i < 4; i++) {
            float2 s = __half22float2(sp[i]);
            float2 p = __half22float2(pp[i]);
            v[2 * i]     = s.x + 0.125f * p.x;
            v[2 * i + 1] = s.y + 0.125f * p.y;
        }
        float mx = v[0];
        #pragma unroll
        for (int i = 1; i < 8; i++) mx = fmaxf(mx, v[i]);
        #pragma unroll
        for (int o = 16; o > 0; o >>= 1) mx = fmaxf(mx, __shfl_xor_sync(0xffffffffu, mx, o));
        float sm = 0.f;
        #pragma unroll
        for (int i = 0; i < 8; i++) { v[i] = __expf(v[i] - mx); sm += v[i]; }
        #pragma unroll
        for (int o = 16; o > 0; o >>= 1) sm += __shfl_xor_sync(0xffffffffu, sm, o);
        float inv = 1.f / sm;
        #pragma unroll
        for (int i = 0; i < 8; i++) Ps[r][lane * 8 + i] = f2t(v[i] * inv);
    }

    // ---- O = P @ V, K=256 in 8 chunks of 32 ----
    const __half* Vb = QKV + (long)(b * 256) * 768 + 512 + h * 64;
    int vR = tid >> 3, vC = (tid & 7) * 8;    // 32 rows x 64 cols, 8 halves/thread
    int wr = w & 1, wc = w >> 1;
    float accO[2][4] = {};
    __syncthreads();   // Ps complete

    #pragma unroll 1
    for (int kc = 0; kc < 8; kc++) {
        uint4 u = *(const uint4*)(Vb + (long)(kc * 32 + vR) * 768 + vC);  // 8 halves
        if (kc > 0) __syncthreads();   // prior mma done reading Vs
        const __half2* hp = (const __half2*)&u;
        #pragma unroll
        for (int i = 0; i < 4; i++) {
            float2 f = __half22float2(hp[i]);
            Vs[vR][vC + 2 * i]     = f2t(f.x);
            Vs[vR][vC + 2 * i + 1] = f2t(f.y);
        }
        __syncthreads();
        #pragma unroll
        for (int ks = 0; ks < 4; ks++) {
            int kk = kc * 32 + ks * 8;
            unsigned a0 = Ps[wr * 16 + g][kk + t];
            unsigned a1 = Ps[wr * 16 + g + 8][kk + t];
            unsigned a2 = Ps[wr * 16 + g][kk + t + 4];
            unsigned a3 = Ps[wr * 16 + g + 8][kk + t + 4];
            #pragma unroll
            for (int ni = 0; ni < 2; ni++) {
                int n0 = wc * 16 + ni * 8 + g;
                unsigned b0 = Vs[ks * 8 + t][n0];
                unsigned b1 = Vs[ks * 8 + t + 4][n0];
                mma8(accO[ni], a0, a1, a2, a3, b0, b1);
            }
        }
    }

    #pragma unroll
    for (int ni = 0; ni < 2; ni++)
        #pragma unroll
        for (int half = 0; half < 2; half++) {
            int r = row0 + wr * 16 + g + half * 8;
            int c = h * 64 + wc * 16 + ni * 8 + 2 * t;
            *(__half2*)(merged + (long)(b * 256 + r) * 256 + c) =
                __floats2half2_rn(accO[ni][half * 2], accO[ni][half * 2 + 1]);
        }
}

// ---------------- split-K reduce + bias + residual (+LN on residual) + stats ----
template<int PPART, int LNRES, int OFF>
__global__ void redres_k(const float* __restrict__ parts, const float* __restrict__ bias,
                         const float* __restrict__ R, float* __restrict__ X,
                         const float* __restrict__ lnw, const float* __restrict__ lnb) {
    __shared__ float shr[2][8];
    int gid = blockIdx.x * 256 + threadIdx.x;       // float4 index < 65536
    int bt = gid >> 14;
    float lnm = 0.f, lnri = 0.f;
    if (LNRES) {
        lnm = g_red[bt * 2] * (1.f / 65536.f);
        float var = g_red[bt * 2 + 1] * (1.f / 65536.f) - lnm * lnm;
        lnri = rsqrtf(var + 1e-5f);
    }
    const float4* pp = (const float4*)parts;
    float4 a = pp[gid];
    #pragma unroll
    for (int p = 1; p < PPART; p++) {
        float4 v = pp[gid + p * (TOT / 4)];
        a.x += v.x; a.y += v.y; a.z += v.z; a.w += v.w;
    }
    float4 bv = ((const float4*)bias)[gid & 63];
    float4 rv = ((const float4*)R)[gid];
    if (LNRES) {
        int p = gid & 16383;
        float4 wv = ((const float4*)lnw)[p];
        float4 lv = ((const float4*)lnb)[p];
        rv.x = (rv.x - lnm) * lnri * wv.x + lv.x;
        rv.y = (rv.y - lnm) * lnri * wv.y + lv.y;
        rv.z = (rv.z - lnm) * lnri * wv.z + lv.z;
        rv.w = (rv.w - lnm) * lnri * wv.w + lv.w;
    }
    a.x += bv.x + rv.x; a.y += bv.y + rv.y; a.z += bv.z + rv.z; a.w += bv.w + rv.w;
    ((float4*)X)[gid] = a;
    float s = a.x + a.y + a.z + a.w;
    float q = a.x * a.x + a.y * a.y + a.z * a.z + a.w * a.w;
    #pragma unroll
    for (int o = 16; o > 0; o >>= 1) {
        s += __shfl_xor_sync(0xffffffffu, s, o);
        q += __shfl_xor_sync(0xffffffffu, q, o);
    }
    int lane = threadIdx.x & 31, wp = threadIdx.x >> 5;
    if (lane == 0) { shr[0][wp] = s; shr[1][wp] = q; }
    __syncthreads();
    if (threadIdx.x == 0) {
        float ts = 0.f, tq = 0.f;
        #pragma unroll
        for (int i = 0; i < 8; i++) { ts += shr[0][i]; tq += shr[1][i]; }
        atomicAdd(&g_red[OFF + bt * 2], ts);
        atomicAdd(&g_red[OFF + bt * 2 + 1], tq);
    }
}

// ---------------- LayerNorm apply (final) ---------------------------------------
__global__ void ln_k(const float* __restrict__ X, const float* __restrict__ w,
                     const float* __restrict__ b, float* __restrict__ out) {
    int gid = blockIdx.x * blockDim.x + threadIdx.x;   // < 65536 float4s
    int bt = gid >> 14;
    float m   = g_red[8 + bt * 2] * (1.f / 65536.f);
    float var = g_red[8 + bt * 2 + 1] * (1.f / 65536.f) - m * m;
    float ri  = rsqrtf(var + 1e-5f);
    int p = gid & 16383;
    float4 x  = ((const float4*)X)[gid];
    float4 wv = ((const float4*)w)[p];
    float4 bv = ((const float4*)b)[p];
    float4 o;
    o.x = (x.x - m) * ri * wv.x + bv.x;
    o.y = (x.y - m) * ri * wv.y + bv.y;
    o.z = (x.z - m) * ri * wv.z + bv.z;
    o.w = (x.w - m) * ri * wv.w + bv.w;
    ((float4*)out)[gid] = o;
}

// ---------------- launch ----------------------------------------------------------
extern "C" void kernel_launch(void* const* d_in, const int* in_sizes, int n_in,
                              void* d_out, int out_size) {
    const float* feat = (const float*)d_in[0];
    const float* loc  = (const float*)d_in[1];
    const float* Kw   = (const float*)d_in[2];
    const float* Kb   = (const float*)d_in[3];
    const float* Qw   = (const float*)d_in[4];
    const float* Qb   = (const float*)d_in[5];
    const float* Vw   = (const float*)d_in[6];
    const float* Vb   = (const float*)d_in[7];
    const float* Fw   = (const float*)d_in[8];
    const float* Fb   = (const float*)d_in[9];
    const float* pe1w = (const float*)d_in[10];
    const float* pe1b = (const float*)d_in[11];
    const float* pe2w = (const float*)d_in[12];
    const float* pe2b = (const float*)d_in[13];
    const float* f1w  = (const float*)d_in[14];
    const float* f1b  = (const float*)d_in[15];
    const float* f2w  = (const float*)d_in[16];
    const float* f2b  = (const float*)d_in[17];
    const float* ln1w = (const float*)d_in[18];
    const float* ln1b = (const float*)d_in[19];
    const float* ln2w = (const float*)d_in[20];
    const float* ln2b = (const float*)d_in[21];
    float* out = (float*)d_out;

    __half *pQKV, *pPsum, *pSh, *pAvp, *pFfnh;
    float *pPart, *pRes1, *pRes2;
    cudaGetSymbolAddress((void**)&pQKV, g_QKVh);
    cudaGetSymbolAddress((void**)&pPsum, g_psumh);
    cudaGetSymbolAddress((void**)&pSh, g_Sh);
    cudaGetSymbolAddress((void**)&pAvp, g_avph);
    cudaGetSymbolAddress((void**)&pFfnh, g_ffnh);
    cudaGetSymbolAddress((void**)&pPart, g_part);
    cudaGetSymbolAddress((void**)&pRes1, g_res1);
    cudaGetSymbolAddress((void**)&pRes2, g_res2);

    static cudaStream_t sPE = nullptr, sV = nullptr;
    static cudaEvent_t evFork = nullptr, evJoin = nullptr, evV = nullptr;
    if (sPE == nullptr) {
        int lo = 0, hi = 0;
        cudaDeviceGetStreamPriorityRange(&lo, &hi);   // lo = lowest priority
        cudaStreamCreateWithPriority(&sPE, cudaStreamNonBlocking, lo);
        cudaStreamCreateWithPriority(&sV, cudaStreamNonBlocking, lo);
        cudaEventCreateWithFlags(&evFork, cudaEventDisableTiming);
        cudaEventCreateWithFlags(&evJoin, cudaEventDisableTiming);
        cudaEventCreateWithFlags(&evV, cudaEventDisableTiming);
    }

    // ---- fork ----
    cudaEventRecord(evFork, 0);
    cudaStreamWaitEvent(sPE, evFork, 0);
    cudaStreamWaitEvent(sV, evFork, 0);

    // PE branch (low priority)
    prep_k<<<1, 128, 0, sPE>>>(pe2w, pe2b);
    pe_k<<<512, 256, 0, sPE>>>(loc, pe1w, pe1b);
    cudaEventRecord(evJoin, sPE);

    // V projection branch (low priority): [1024,256] @ Vw -> QKVh cols [512,768)
    gtc<64, 0, EPI_BIAS, 0, 4, 0, 0, 1, 0, 0><<<dim3(4, 16, 1), 128, 0, sV>>>(
        feat, nullptr, Vw, nullptr, nullptr, Vb, nullptr, nullptr,
        pQKV + 512, nullptr, nullptr,
        256, 256, 256, 768, 0, 0, 0, 0, 0, 0, 0);
    cudaEventRecord(evV, sV);

    // ---- main branch ----
    // QK: [1024,256] @ {Qw|Kw} -> QKVh cols [0,512), BM=64, grid 128
    gtc<64, 0, EPI_BIAS, 0, 8, 0, 0, 1, 0, 1><<<dim3(8, 16, 1), 128>>>(
        feat, nullptr, Qw, Kw, nullptr, Qb, Kb, nullptr,
        pQKV, nullptr, nullptr,
        256, 256, 256, 768, 0, 0, 0, 0, 0, 0, 0);

    // scores: per (b,h) K-rows · Q-rows^T * 0.125 -> Sh (half), grid 512
    gtc<32, 1, EPI_SCL, 0, 4, 1, 1, 1, 0, 0><<<dim3(4, 8, 16), 128>>>(
        pQKV + 256, nullptr, pQKV, nullptr, nullptr, nullptr, nullptr, nullptr,
        pSh, nullptr, nullptr,
        64, 768, 768, 256, 196608, 64, 196608, 64, 262144, 65536, 0);

    // joins: smav needs psum (PE) and V
    cudaStreamWaitEvent(0, evJoin, 0);
    cudaStreamWaitEvent(0, evV, 0);

    // fused softmax + AV -> merged (half), grid 128
    smav_k<<<dim3(8, 16), 256>>>(pSh, pPsum, pQKV, pAvp);

    // output projection: A = merged (half), split-K 2 -> part fp32
    gtc<64, 0, EPI_NONE, 0, 4, 1, 0, 0, 0, 0><<<dim3(8, 16, 1), 128>>>(
        pAvp, nullptr, Fw, nullptr, nullptr, nullptr, nullptr, nullptr,
        pPart, nullptr, nullptr,
        128, 256, 256, 256, 0, 0, 0, 0, 0, 0, TOT);

    // reduce + Fb + feat residual -> res1, LN1 stats -> red[0..7]
    redres_k<2, 0, 0><<<256, 256>>>(pPart, Fb, feat, pRes1, nullptr, nullptr);

    // FFN1: A = LN1(res1) on load; bias+relu -> ffnh (half)
    gtc<64, 0, EPI_BRELU, 0, 16, 0, 0, 1, 1, 0><<<dim3(16, 16, 1), 128>>>(
        pRes1, nullptr, f1w, nullptr, nullptr, f1b, nullptr, nullptr,
        pFfnh, ln1w, ln1b,
        256, 256, 1024, 1024, 0, 0, 0, 0, 0, 0, 0);

    // FFN2: A = ffnh (half), split-K 4 -> part fp32
    gtc<64, 0, EPI_NONE, 0, 4, 1, 0, 0, 0, 0><<<dim3(16, 16, 1), 128>>>(
        pFfnh, nullptr, f2w, nullptr, nullptr, nullptr, nullptr, nullptr,
        pPart, nullptr, nullptr,
        256, 1024, 256, 256, 0, 0, 0, 0, 0, 0, TOT);

    // reduce + f2b + LN1(res1) residual -> res2, LN2 stats -> red[8..15]
    redres_k<4, 1, 8><<<256, 256>>>(pPart, f2b, pRes1, pRes2, ln1w, ln1b);

    // final LN2 -> out
    ln_k<<<256, 256>>>(pRes2, ln2w, ln2b, out);
}